// round 2
// baseline (speedup 1.0000x reference)
#include <cuda_runtime.h>
#include <math.h>

#define BB 4
#define TT 2048
#define CC 2048
#define HH 128
#define EE 16
#define NN (BB * TT)   // 8192 tokens

#define NEGINF (__int_as_float(0xff800000u))

// ---------------- scratch (device globals; no allocation allowed) ----------
__device__ float g_q[NN * HH];
__device__ float g_k[NN * HH];
__device__ float g_v[NN * HH];
__device__ float g_attn[NN * HH];
__device__ float g_invsnorm[EE];
__device__ int   g_cnt[EE];
__device__ int   g_tok[EE * NN];
__device__ float g_twt[EE * NN];

// ---------------- zero kernels --------------------------------------------
__global__ void zero4_kernel(float4* p, int n4) {
    int i = blockIdx.x * blockDim.x + threadIdx.x;
    int stride = gridDim.x * blockDim.x;
    float4 z = make_float4(0.f, 0.f, 0.f, 0.f);
    for (; i < n4; i += stride) p[i] = z;
}

__global__ void zero_scratch_kernel() {
    int i = blockIdx.x * blockDim.x + threadIdx.x;
    int stride = gridDim.x * blockDim.x;
    for (int j = i; j < NN * HH; j += stride) {
        g_q[j] = 0.f; g_k[j] = 0.f; g_v[j] = 0.f;
    }
    if (i < EE) g_cnt[i] = 0;
}

// ---------------- sim_matrix column inverse norms -------------------------
__global__ void colnorm_kernel(const float* __restrict__ sim) {
    int tid = threadIdx.x;
    float acc[EE];
#pragma unroll
    for (int e = 0; e < EE; e++) acc[e] = 0.f;
    for (int c = tid; c < CC; c += 256) {
        float sv[EE];
        const float4* row = reinterpret_cast<const float4*>(sim + (size_t)c * EE);
#pragma unroll
        for (int q = 0; q < 4; q++) *reinterpret_cast<float4*>(&sv[q * 4]) = row[q];
#pragma unroll
        for (int e = 0; e < EE; e++) acc[e] += sv[e] * sv[e];
    }
#pragma unroll
    for (int off = 16; off; off >>= 1)
#pragma unroll
        for (int e = 0; e < EE; e++)
            acc[e] += __shfl_xor_sync(0xffffffffu, acc[e], off);
    __shared__ float ws[8][EE];
    if ((tid & 31) == 0)
#pragma unroll
        for (int e = 0; e < EE; e++) ws[tid >> 5][e] = acc[e];
    __syncthreads();
    if (tid < EE) {
        float s = 0.f;
#pragma unroll
        for (int w = 0; w < 8; w++) s += ws[w][tid];
        g_invsnorm[tid] = 1.f / fmaxf(sqrtf(s), 1e-12f);
    }
}

// ---------------- gating: one block (128 thr) per token -------------------
// Faithful implementation of relu-mask + top-k fallback + softmax.
// Emits per-expert token lists (g_tok) and routing weights (g_twt).
__global__ void gating_kernel(const float* __restrict__ x,
                              const float* __restrict__ sim,
                              const float* __restrict__ gates,
                              const int* __restrict__ min_experts_p) {
    int n = blockIdx.x;
    int tid = threadIdx.x;
    float dot[EE];
#pragma unroll
    for (int e = 0; e < EE; e++) dot[e] = 0.f;
    float xx = 0.f;
    const float* xr = x + (size_t)n * CC;
    for (int c = tid; c < CC; c += 128) {
        float xv = xr[c];
        xx += xv * xv;
        float sv[EE];
        const float4* row = reinterpret_cast<const float4*>(sim + (size_t)c * EE);
#pragma unroll
        for (int q = 0; q < 4; q++) *reinterpret_cast<float4*>(&sv[q * 4]) = row[q];
#pragma unroll
        for (int e = 0; e < EE; e++) dot[e] += xv * sv[e];
    }
#pragma unroll
    for (int off = 16; off; off >>= 1) {
        xx += __shfl_xor_sync(0xffffffffu, xx, off);
#pragma unroll
        for (int e = 0; e < EE; e++)
            dot[e] += __shfl_xor_sync(0xffffffffu, dot[e], off);
    }
    __shared__ float ws[4][EE + 1];
    if ((tid & 31) == 0) {
#pragma unroll
        for (int e = 0; e < EE; e++) ws[tid >> 5][e] = dot[e];
        ws[tid >> 5][EE] = xx;
    }
    __syncthreads();
    __shared__ float tot[EE + 1];
    if (tid < EE + 1)
        tot[tid] = ws[0][tid] + ws[1][tid] + ws[2][tid] + ws[3][tid];
    __syncthreads();

    if (tid < 32) {
        int e = tid;
        bool isE = (e < EE);
        float invx = 1.f / fmaxf(sqrtf(tot[EE]), 1e-12f);
        float logit = NEGINF;
        if (isE) {
            float sig = 1.f / (1.f + __expf(-gates[e]));
            logit = tot[e] * invx * g_invsnorm[e] - sig;
        }
        float gated = fmaxf(logit, 0.f);
        bool sel = isE && (logit > 0.f);
        unsigned act = __ballot_sync(0xffffffffu, sel);
        if (act == 0u) {
            int kreq = *min_experts_p;
            kreq = max(1, min(kreq, EE));
            bool chosen = false;
            for (int it = 0; it < kreq; it++) {
                float cand = (isE && !chosen) ? logit : NEGINF;
                float mv = cand;
#pragma unroll
                for (int off = 16; off; off >>= 1)
                    mv = fmaxf(mv, __shfl_xor_sync(0xffffffffu, mv, off));
                unsigned bal = __ballot_sync(0xffffffffu, (cand == mv) && (mv != NEGINF));
                int lane = __ffs(bal) - 1;  // lowest index wins ties (matches jax top_k)
                if (tid == lane) chosen = true;
            }
            sel = chosen;
        }
        float ml = sel ? gated : NEGINF;
        float mv = ml;
#pragma unroll
        for (int off = 16; off; off >>= 1)
            mv = fmaxf(mv, __shfl_xor_sync(0xffffffffu, mv, off));
        float p = sel ? __expf(gated - mv) : 0.f;
        float sum = p;
#pragma unroll
        for (int off = 16; off; off >>= 1)
            sum += __shfl_xor_sync(0xffffffffu, sum, off);
        if (sel) {
            float w = p / sum;
            int pos = atomicAdd(&g_cnt[e], 1);
            g_tok[e * NN + pos] = n;
            g_twt[e * NN + pos] = w;
        }
    }
}

// ---------------- grouped (gathered) GEMM with weighted scatter -----------
// Per expert e: Out[tok, cb:cb+128] += w_tok * A[tok, :K] @ B_e[:K, cb:cb+128]
// 64x128 tile, K-chunks of 16, fp32 smem micro-kernel (4x8 per thread).
template <int K, int LDB>
__global__ void __launch_bounds__(256)
grouped_gemm_kernel(const float* __restrict__ Aarg, int asel, int lda,
                    const float* __restrict__ B0,
                    float* __restrict__ OutArg, int outsel, int ldo) {
    const int e = blockIdx.z;
    const int m = g_cnt[e];
    const int row0 = blockIdx.x * 64;
    if (row0 >= m) return;
    const float* A = (asel == 0) ? Aarg : g_attn;
    float* Out = (outsel == 0) ? g_q : (outsel == 1) ? g_k : (outsel == 2) ? g_v : OutArg;
    const int cb = blockIdx.y * 128;
    const float* Bmat = B0 + (size_t)e * K * LDB + cb;

    __shared__ float As[16][68];
    __shared__ float Bs[16][128];

    const int tid = threadIdx.x;
    const int tm = tid >> 4;   // 0..15 -> rows tm*4 .. tm*4+3
    const int tn = tid & 15;   // 0..15 -> cols tn*8 .. tn*8+7

    float acc[4][8];
#pragma unroll
    for (int i = 0; i < 4; i++)
#pragma unroll
        for (int j = 0; j < 8; j++) acc[i][j] = 0.f;

    // A staging: thread (kA=tid&15, rA=tid>>4) loads rows rA+16i
    const int kA = tid & 15;
    const int rA = tid >> 4;
    const float* aptr[4];
#pragma unroll
    for (int i = 0; i < 4; i++) {
        int gr = row0 + rA + i * 16;
        int tok = g_tok[e * NN + ((gr < m) ? gr : row0)];  // clamp pad rows (valid mem)
        aptr[i] = A + (size_t)tok * lda + kA;
    }
    const int bh = (tid & 31) * 4;
    const int bk = tid >> 5;  // 0..7

    for (int k0 = 0; k0 < K; k0 += 16) {
#pragma unroll
        for (int i = 0; i < 4; i++) As[kA][rA + i * 16] = aptr[i][k0];
#pragma unroll
        for (int i = 0; i < 2; i++) {
            int kr = bk + i * 8;
            *reinterpret_cast<float4*>(&Bs[kr][bh]) =
                *reinterpret_cast<const float4*>(Bmat + (size_t)(k0 + kr) * LDB + bh);
        }
        __syncthreads();
#pragma unroll
        for (int kk = 0; kk < 16; kk++) {
            float4 av = *reinterpret_cast<const float4*>(&As[kk][tm * 4]);
            float4 b0 = *reinterpret_cast<const float4*>(&Bs[kk][tn * 8]);
            float4 b1 = *reinterpret_cast<const float4*>(&Bs[kk][tn * 8 + 4]);
            float a[4] = {av.x, av.y, av.z, av.w};
            float b[8] = {b0.x, b0.y, b0.z, b0.w, b1.x, b1.y, b1.z, b1.w};
#pragma unroll
            for (int i = 0; i < 4; i++)
#pragma unroll
                for (int j = 0; j < 8; j++) acc[i][j] += a[i] * b[j];
        }
        __syncthreads();
    }
#pragma unroll
    for (int i = 0; i < 4; i++) {
        int gr = row0 + tm * 4 + i;
        if (gr < m) {
            int tok = g_tok[e * NN + gr];
            float w = g_twt[e * NN + gr];
            float* orow = Out + (size_t)tok * ldo + cb + tn * 8;
#pragma unroll
            for (int j = 0; j < 8; j++) atomicAdd(&orow[j], w * acc[i][j]);
        }
    }
}

// ---------------- flash attention (causal, single head per batch) ---------
#define TQ 64
#define TK 32
#define QPAD 129
#define KTPAD 36
#define SPAD 33

__global__ void __launch_bounds__(256) attn_kernel() {
    extern __shared__ float sm[];
    float* Qs = sm;                      // [TQ][QPAD]
    float* Kt = Qs + TQ * QPAD;          // [HH][KTPAD]  (K transposed)
    float* Vs = Kt + HH * KTPAD;         // [TK][HH]
    float* Ss = Vs + TK * HH;            // [TQ][SPAD]
    float* mrow = Ss + TQ * SPAD;        // [TQ]
    float* lrow = mrow + TQ;             // [TQ]
    float* crow = lrow + TQ;             // [TQ]

    int b = blockIdx.y;
    int q0 = blockIdx.x * TQ;
    int tid = threadIdx.x;
    const float scale = 0.08838834764831845f;  // 1/sqrt(128)

    size_t qbase = ((size_t)(b * TT + q0)) * HH;
    for (int idx = tid; idx < TQ * HH; idx += 256) {
        int r = idx >> 7, h = idx & 127;
        Qs[r * QPAD + h] = g_q[qbase + idx];
    }
    if (tid < TQ) { mrow[tid] = NEGINF; lrow[tid] = 0.f; }

    int tm = tid >> 4, tn = tid & 15;
    float oacc[4][8];
#pragma unroll
    for (int i = 0; i < 4; i++)
#pragma unroll
        for (int j = 0; j < 8; j++) oacc[i][j] = 0.f;

    int tr = tid >> 3, tc = tid & 7;
    int ntiles = (q0 + TQ - 1) / TK + 1;

    for (int t = 0; t < ntiles; t++) {
        int j0 = t * TK;
        size_t kbase = ((size_t)(b * TT + j0)) * HH;
        __syncthreads();  // prior tile's consumers done before overwrite
        for (int idx = tid; idx < TK * HH; idx += 256) {
            int r = idx >> 7, h = idx & 127;
            Kt[h * KTPAD + r] = g_k[kbase + idx];
        }
        for (int idx = tid; idx < TK * HH / 4; idx += 256)
            reinterpret_cast<float4*>(Vs)[idx] =
                reinterpret_cast<const float4*>(g_v + kbase)[idx];
        __syncthreads();

        // S = scale * Q K^T with causal mask; thread computes 2x4 tile
        {
            float s[2][4];
#pragma unroll
            for (int i = 0; i < 2; i++)
#pragma unroll
                for (int j = 0; j < 4; j++) s[i][j] = 0.f;
            for (int h = 0; h < HH; h++) {
                float qa = Qs[(tr * 2) * QPAD + h];
                float qb = Qs[(tr * 2 + 1) * QPAD + h];
                const float* kp = &Kt[h * KTPAD + tc * 4];
                float k0 = kp[0], k1 = kp[1], k2 = kp[2], k3 = kp[3];
                s[0][0] += qa * k0; s[0][1] += qa * k1; s[0][2] += qa * k2; s[0][3] += qa * k3;
                s[1][0] += qb * k0; s[1][1] += qb * k1; s[1][2] += qb * k2; s[1][3] += qb * k3;
            }
#pragma unroll
            for (int i = 0; i < 2; i++) {
                int qi = q0 + tr * 2 + i;
#pragma unroll
                for (int j = 0; j < 4; j++) {
                    int ki = j0 + tc * 4 + j;
                    Ss[(tr * 2 + i) * SPAD + tc * 4 + j] =
                        (ki <= qi) ? s[i][j] * scale : NEGINF;
                }
            }
        }
        __syncthreads();

        // online softmax stats; thread r owns row r
        if (tid < TQ) {
            int r = tid;
            float mold = mrow[r];
            float tmax = NEGINF;
#pragma unroll
            for (int c = 0; c < TK; c++) tmax = fmaxf(tmax, Ss[r * SPAD + c]);
            float mnew = fmaxf(mold, tmax);
            float corr = __expf(mold - mnew);  // 0 on first tile (mold=-inf)
            float sum = 0.f;
#pragma unroll
            for (int c = 0; c < TK; c++) {
                float pv = __expf(Ss[r * SPAD + c] - mnew);
                Ss[r * SPAD + c] = pv;
                sum += pv;
            }
            lrow[r] = lrow[r] * corr + sum;
            mrow[r] = mnew;
            crow[r] = corr;
        }
        __syncthreads();

        // O = O*corr + P V
#pragma unroll
        for (int i = 0; i < 4; i++) {
            float cr = crow[tm * 4 + i];
#pragma unroll
            for (int j = 0; j < 8; j++) oacc[i][j] *= cr;
        }
        for (int jj = 0; jj < TK; jj++) {
            float4 v0 = *reinterpret_cast<const float4*>(&Vs[jj * HH + tn * 8]);
            float4 v1 = *reinterpret_cast<const float4*>(&Vs[jj * HH + tn * 8 + 4]);
#pragma unroll
            for (int i = 0; i < 4; i++) {
                float pv = Ss[(tm * 4 + i) * SPAD + jj];
                oacc[i][0] += pv * v0.x; oacc[i][1] += pv * v0.y;
                oacc[i][2] += pv * v0.z; oacc[i][3] += pv * v0.w;
                oacc[i][4] += pv * v1.x; oacc[i][5] += pv * v1.y;
                oacc[i][6] += pv * v1.z; oacc[i][7] += pv * v1.w;
            }
        }
    }

#pragma unroll
    for (int i = 0; i < 4; i++) {
        int r = tm * 4 + i;
        float inv = 1.f / lrow[r];
        float* orow = g_attn + ((size_t)(b * TT + q0 + r)) * HH + tn * 8;
        *reinterpret_cast<float4*>(orow) =
            make_float4(oacc[i][0] * inv, oacc[i][1] * inv, oacc[i][2] * inv, oacc[i][3] * inv);
        *reinterpret_cast<float4*>(orow + 4) =
            make_float4(oacc[i][4] * inv, oacc[i][5] * inv, oacc[i][6] * inv, oacc[i][7] * inv);
    }
}

// ---------------- launch ---------------------------------------------------
extern "C" void kernel_launch(void* const* d_in, const int* in_sizes, int n_in,
                              void* d_out, int out_size) {
    const float* x   = (const float*)d_in[0];
    const float* sim = (const float*)d_in[1];
    const float* gts = (const float*)d_in[2];
    const float* qp  = (const float*)d_in[3];
    const float* kp  = (const float*)d_in[4];
    const float* vp  = (const float*)d_in[5];
    const float* op  = (const float*)d_in[6];
    const int* minexp = (const int*)d_in[7];
    float* out = (float*)d_out;

    const int attn_smem =
        (TQ * QPAD + HH * KTPAD + TK * HH + TQ * SPAD + 3 * TQ) * (int)sizeof(float);
    cudaFuncSetAttribute((const void*)attn_kernel,
                         cudaFuncAttributeMaxDynamicSharedMemorySize, attn_smem);

    zero4_kernel<<<4096, 256>>>((float4*)out, (NN * CC) / 4);
    zero_scratch_kernel<<<2048, 256>>>();
    colnorm_kernel<<<1, 256>>>(sim);
    gating_kernel<<<NN, 128>>>(x, sim, gts, minexp);

    dim3 gq(NN / 64, 1, EE);
    grouped_gemm_kernel<CC, HH><<<gq, 256>>>(x, 0, CC, qp, nullptr, 0, HH);
    grouped_gemm_kernel<CC, HH><<<gq, 256>>>(x, 0, CC, kp, nullptr, 1, HH);
    grouped_gemm_kernel<CC, HH><<<gq, 256>>>(x, 0, CC, vp, nullptr, 2, HH);

    attn_kernel<<<dim3(TT / TQ, BB), 256, attn_smem>>>();

    dim3 go(NN / 64, CC / 128, EE);
    grouped_gemm_kernel<HH, CC><<<go, 256>>>(nullptr, 1, HH, op, out, 3, CC);
}

// round 3
// speedup vs baseline: 2.8294x; 2.8294x over previous
#include <cuda_runtime.h>
#include <math.h>

#define BB 4
#define TT 2048
#define CC 2048
#define HH 128
#define EE 16
#define NN (BB * TT)   // 8192 tokens
#define NQT (TT / 64)  // 32 q-tiles per batch
#define NEGINF (__int_as_float(0xff800000u))

// ---------------- scratch (device globals; no allocation allowed) ----------
__device__ float g_q[NN * HH];
__device__ float g_k[NN * HH];
__device__ float g_v[NN * HH];
__device__ float g_attn[NN * HH];
__device__ float g_invsnorm[EE];
__device__ int   g_cnt[EE];
__device__ int   g_tok[EE * NN];
__device__ float g_twt[EE * NN];
__device__ float g_logits[NN * EE];
__device__ float g_xx[NN];
// attention split-KV partials: [B][qt][chunk<=4][64 rows][128]
__device__ float g_pO[BB * NQT * 4 * 64 * HH];
__device__ float g_pm[BB * NQT * 4 * 64];
__device__ float g_pl[BB * NQT * 4 * 64];

// ---------------- helpers ---------------------------------------------------
__device__ __forceinline__ unsigned f2tf(float f) {
    unsigned r;
    asm("cvt.rna.tf32.f32 %0, %1;" : "=r"(r) : "f"(f));
    return r;
}
__device__ __forceinline__ void mma_tf32(float* d, const unsigned* a, const unsigned* b) {
    asm volatile(
        "mma.sync.aligned.m16n8k8.row.col.f32.tf32.tf32.f32 "
        "{%0,%1,%2,%3},{%4,%5,%6,%7},{%8,%9},{%0,%1,%2,%3};"
        : "+f"(d[0]), "+f"(d[1]), "+f"(d[2]), "+f"(d[3])
        : "r"(a[0]), "r"(a[1]), "r"(a[2]), "r"(a[3]), "r"(b[0]), "r"(b[1]));
}

// ---------------- zero kernels --------------------------------------------
__global__ void zero4_kernel(float4* p, int n4) {
    int i = blockIdx.x * blockDim.x + threadIdx.x;
    int stride = gridDim.x * blockDim.x;
    float4 z = make_float4(0.f, 0.f, 0.f, 0.f);
    for (; i < n4; i += stride) p[i] = z;
}
__global__ void zero_scratch_kernel() {
    int i = blockIdx.x * blockDim.x + threadIdx.x;
    int stride = gridDim.x * blockDim.x;
    for (int j = i; j < NN * HH; j += stride) {
        g_q[j] = 0.f; g_k[j] = 0.f; g_v[j] = 0.f;
    }
    if (i < EE) g_cnt[i] = 0;
}

// ---------------- sim_matrix column inverse norms -------------------------
__global__ void colnorm_kernel(const float* __restrict__ sim) {
    int tid = threadIdx.x;
    float acc[EE];
#pragma unroll
    for (int e = 0; e < EE; e++) acc[e] = 0.f;
    for (int c = tid; c < CC; c += 256) {
        float sv[EE];
        const float4* row = reinterpret_cast<const float4*>(sim + (size_t)c * EE);
#pragma unroll
        for (int q = 0; q < 4; q++) *reinterpret_cast<float4*>(&sv[q * 4]) = row[q];
#pragma unroll
        for (int e = 0; e < EE; e++) acc[e] += sv[e] * sv[e];
    }
#pragma unroll
    for (int off = 16; off; off >>= 1)
#pragma unroll
        for (int e = 0; e < EE; e++)
            acc[e] += __shfl_xor_sync(0xffffffffu, acc[e], off);
    __shared__ float ws[8][EE];
    if ((tid & 31) == 0)
#pragma unroll
        for (int e = 0; e < EE; e++) ws[tid >> 5][e] = acc[e];
    __syncthreads();
    if (tid < EE) {
        float s = 0.f;
#pragma unroll
        for (int w = 0; w < 8; w++) s += ws[w][tid];
        g_invsnorm[tid] = 1.f / fmaxf(sqrtf(s), 1e-12f);
    }
}

// ---------------- logits: 64 tokens/block, sim chunk in smem --------------
__global__ void __launch_bounds__(256) logits_kernel(const float* __restrict__ x,
                                                     const float* __restrict__ sim) {
    __shared__ float Xs[64][132];
    __shared__ float Ss[128][16];
    int n0 = blockIdx.x * 64;
    int tid = threadIdx.x;
    int tok = tid >> 2;
    int eg = tid & 3;
    float acc[4] = {0.f, 0.f, 0.f, 0.f};
    float xx = 0.f;
    for (int c0 = 0; c0 < CC; c0 += 128) {
        __syncthreads();
        for (int i = tid; i < 512; i += 256)
            reinterpret_cast<float4*>(&Ss[0][0])[i] =
                reinterpret_cast<const float4*>(sim + (size_t)c0 * EE)[i];
        for (int i = tid; i < 2048; i += 256) {
            int r = i >> 5, k4 = i & 31;
            *reinterpret_cast<float4*>(&Xs[r][k4 * 4]) =
                *reinterpret_cast<const float4*>(x + (size_t)(n0 + r) * CC + c0 + k4 * 4);
        }
        __syncthreads();
#pragma unroll 4
        for (int k = 0; k < 128; k++) {
            float xv = Xs[tok][k];
            float4 sv = *reinterpret_cast<const float4*>(&Ss[k][eg * 4]);
            acc[0] += xv * sv.x; acc[1] += xv * sv.y;
            acc[2] += xv * sv.z; acc[3] += xv * sv.w;
            if (eg == 0) xx += xv * xv;
        }
    }
    int n = n0 + tok;
    *reinterpret_cast<float4*>(&g_logits[(size_t)n * EE + eg * 4]) =
        make_float4(acc[0], acc[1], acc[2], acc[3]);
    if (eg == 0) g_xx[n] = xx;
}

// ---------------- selection: warp per token -------------------------------
__global__ void __launch_bounds__(256) select_kernel(const float* __restrict__ gates,
                                                     const int* __restrict__ min_experts_p) {
    int n = blockIdx.x * 8 + (threadIdx.x >> 5);
    int lane = threadIdx.x & 31;
    bool isE = (lane < EE);
    float invx = 1.f / fmaxf(sqrtf(g_xx[n]), 1e-12f);
    float logit = NEGINF;
    if (isE) {
        float sig = 1.f / (1.f + __expf(-gates[lane]));
        logit = g_logits[(size_t)n * EE + lane] * invx * g_invsnorm[lane] - sig;
    }
    float gated = fmaxf(logit, 0.f);
    bool sel = isE && (logit > 0.f);
    unsigned act = __ballot_sync(0xffffffffu, sel);
    if (act == 0u) {
        int kreq = *min_experts_p;
        kreq = max(1, min(kreq, EE));
        bool chosen = false;
        for (int it = 0; it < kreq; it++) {
            float cand = (isE && !chosen) ? logit : NEGINF;
            float mv = cand;
#pragma unroll
            for (int off = 16; off; off >>= 1)
                mv = fmaxf(mv, __shfl_xor_sync(0xffffffffu, mv, off));
            unsigned bal = __ballot_sync(0xffffffffu, (cand == mv) && (mv != NEGINF));
            int ln = __ffs(bal) - 1;
            if (lane == ln) chosen = true;
        }
        sel = chosen;
    }
    float ml = sel ? gated : NEGINF;
    float mv = ml;
#pragma unroll
    for (int off = 16; off; off >>= 1)
        mv = fmaxf(mv, __shfl_xor_sync(0xffffffffu, mv, off));
    float p = sel ? __expf(gated - mv) : 0.f;
    float sum = p;
#pragma unroll
    for (int off = 16; off; off >>= 1)
        sum += __shfl_xor_sync(0xffffffffu, sum, off);
    if (sel) {
        float w = p / sum;
        int pos = atomicAdd(&g_cnt[lane], 1);
        g_tok[lane * NN + pos] = n;
        g_twt[lane * NN + pos] = w;
    }
}

// ---------------- fused QKV grouped GEMM (tf32 mma) ------------------------
// grid (NN/64, 3, EE); block 256. Tile 64x128, K=2048 in chunks of 32.
__global__ void __launch_bounds__(256)
qkv_mma_kernel(const float* __restrict__ x, const float* __restrict__ qp,
               const float* __restrict__ kp, const float* __restrict__ vp) {
    const int e = blockIdx.z;
    const int m = g_cnt[e];
    const int row0 = blockIdx.x * 64;
    if (row0 >= m) return;
    const int p = blockIdx.y;
    const float* B = ((p == 0) ? qp : (p == 1) ? kp : vp) + (size_t)e * CC * HH;
    float* Out = (p == 0) ? g_q : (p == 1) ? g_k : g_v;

    __shared__ unsigned As[64 * 36];   // [m][k] stride 36
    __shared__ unsigned Bs[32 * 136];  // [k][n] stride 136

    const int tid = threadIdx.x, lane = tid & 31, w = tid >> 5;
    const int wm = w & 1, wn = w >> 1;
    const int g = lane >> 2, t = lane & 3;

    float acc[2][4][4];
#pragma unroll
    for (int mt = 0; mt < 2; mt++)
#pragma unroll
        for (int nt = 0; nt < 4; nt++)
#pragma unroll
            for (int i = 0; i < 4; i++) acc[mt][nt][i] = 0.f;

    const int ar = tid >> 2, akb = (tid & 3) * 8;
    int gr = row0 + ar;
    int tok = g_tok[e * NN + ((gr < m) ? gr : (m - 1))];
    const float* aptr = x + (size_t)tok * CC + akb;
    const int br = tid >> 3, bnb = (tid & 7) * 16;
    const float* bptr = B + (size_t)br * HH + bnb;

    for (int k0 = 0; k0 < CC; k0 += 32) {
        float4 av0 = *reinterpret_cast<const float4*>(aptr + k0);
        float4 av1 = *reinterpret_cast<const float4*>(aptr + k0 + 4);
        float4 bv[4];
#pragma unroll
        for (int j = 0; j < 4; j++)
            bv[j] = *reinterpret_cast<const float4*>(bptr + (size_t)k0 * HH + j * 4);
        __syncthreads();
        {
            uint4 u0 = make_uint4(f2tf(av0.x), f2tf(av0.y), f2tf(av0.z), f2tf(av0.w));
            uint4 u1 = make_uint4(f2tf(av1.x), f2tf(av1.y), f2tf(av1.z), f2tf(av1.w));
            *reinterpret_cast<uint4*>(&As[ar * 36 + akb]) = u0;
            *reinterpret_cast<uint4*>(&As[ar * 36 + akb + 4]) = u1;
#pragma unroll
            for (int j = 0; j < 4; j++) {
                uint4 ub = make_uint4(f2tf(bv[j].x), f2tf(bv[j].y), f2tf(bv[j].z), f2tf(bv[j].w));
                *reinterpret_cast<uint4*>(&Bs[br * 136 + bnb + j * 4]) = ub;
            }
        }
        __syncthreads();
#pragma unroll
        for (int kk = 0; kk < 4; kk++) {
            unsigned afr[2][4], bfr[4][2];
#pragma unroll
            for (int mt = 0; mt < 2; mt++) {
                int ab = (wm * 32 + mt * 16 + g) * 36 + kk * 8 + t;
                afr[mt][0] = As[ab];       afr[mt][1] = As[ab + 288];
                afr[mt][2] = As[ab + 4];   afr[mt][3] = As[ab + 292];
            }
#pragma unroll
            for (int nt = 0; nt < 4; nt++) {
                int col = wn * 32 + nt * 8 + g;
                int bb = (kk * 8 + t) * 136 + col;
                bfr[nt][0] = Bs[bb];
                bfr[nt][1] = Bs[bb + 544];
            }
#pragma unroll
            for (int mt = 0; mt < 2; mt++)
#pragma unroll
                for (int nt = 0; nt < 4; nt++) mma_tf32(acc[mt][nt], afr[mt], bfr[nt]);
        }
    }
#pragma unroll
    for (int mt = 0; mt < 2; mt++) {
        int r0 = row0 + wm * 32 + mt * 16 + g;
#pragma unroll
        for (int half = 0; half < 2; half++) {
            int grr = r0 + half * 8;
            if (grr < m) {
                int tk = g_tok[e * NN + grr];
                float wgt = g_twt[e * NN + grr];
                float* orow = Out + (size_t)tk * HH;
#pragma unroll
                for (int nt = 0; nt < 4; nt++) {
                    int c = wn * 32 + nt * 8 + t * 2;
                    atomicAdd(&orow[c],     wgt * acc[mt][nt][half * 2]);
                    atomicAdd(&orow[c + 1], wgt * acc[mt][nt][half * 2 + 1]);
                }
            }
        }
    }
}

// ---------------- o-proj grouped GEMM (tf32 mma) ---------------------------
// grid (NN/64, CC/128, EE); K = HH = 128.
__global__ void __launch_bounds__(256)
oproj_mma_kernel(const float* __restrict__ op, float* __restrict__ out) {
    const int e = blockIdx.z;
    const int m = g_cnt[e];
    const int row0 = blockIdx.x * 64;
    if (row0 >= m) return;
    const int cb = blockIdx.y * 128;
    const float* B = op + (size_t)e * HH * CC + cb;

    __shared__ unsigned As[64 * 36];
    __shared__ unsigned Bs[32 * 136];

    const int tid = threadIdx.x, lane = tid & 31, w = tid >> 5;
    const int wm = w & 1, wn = w >> 1;
    const int g = lane >> 2, t = lane & 3;

    float acc[2][4][4];
#pragma unroll
    for (int mt = 0; mt < 2; mt++)
#pragma unroll
        for (int nt = 0; nt < 4; nt++)
#pragma unroll
            for (int i = 0; i < 4; i++) acc[mt][nt][i] = 0.f;

    const int ar = tid >> 2, akb = (tid & 3) * 8;
    int gr = row0 + ar;
    int tok = g_tok[e * NN + ((gr < m) ? gr : (m - 1))];
    const float* aptr = g_attn + (size_t)tok * HH + akb;
    const int br = tid >> 3, bnb = (tid & 7) * 16;
    const float* bptr = B + (size_t)br * CC + bnb;

    for (int k0 = 0; k0 < HH; k0 += 32) {
        float4 av0 = *reinterpret_cast<const float4*>(aptr + k0);
        float4 av1 = *reinterpret_cast<const float4*>(aptr + k0 + 4);
        float4 bv[4];
#pragma unroll
        for (int j = 0; j < 4; j++)
            bv[j] = *reinterpret_cast<const float4*>(bptr + (size_t)k0 * CC + j * 4);
        __syncthreads();
        {
            uint4 u0 = make_uint4(f2tf(av0.x), f2tf(av0.y), f2tf(av0.z), f2tf(av0.w));
            uint4 u1 = make_uint4(f2tf(av1.x), f2tf(av1.y), f2tf(av1.z), f2tf(av1.w));
            *reinterpret_cast<uint4*>(&As[ar * 36 + akb]) = u0;
            *reinterpret_cast<uint4*>(&As[ar * 36 + akb + 4]) = u1;
#pragma unroll
            for (int j = 0; j < 4; j++) {
                uint4 ub = make_uint4(f2tf(bv[j].x), f2tf(bv[j].y), f2tf(bv[j].z), f2tf(bv[j].w));
                *reinterpret_cast<uint4*>(&Bs[br * 136 + bnb + j * 4]) = ub;
            }
        }
        __syncthreads();
#pragma unroll
        for (int kk = 0; kk < 4; kk++) {
            unsigned afr[2][4], bfr[4][2];
#pragma unroll
            for (int mt = 0; mt < 2; mt++) {
                int ab = (wm * 32 + mt * 16 + g) * 36 + kk * 8 + t;
                afr[mt][0] = As[ab];       afr[mt][1] = As[ab + 288];
                afr[mt][2] = As[ab + 4];   afr[mt][3] = As[ab + 292];
            }
#pragma unroll
            for (int nt = 0; nt < 4; nt++) {
                int col = wn * 32 + nt * 8 + g;
                int bb = (kk * 8 + t) * 136 + col;
                bfr[nt][0] = Bs[bb];
                bfr[nt][1] = Bs[bb + 544];
            }
#pragma unroll
            for (int mt = 0; mt < 2; mt++)
#pragma unroll
                for (int nt = 0; nt < 4; nt++) mma_tf32(acc[mt][nt], afr[mt], bfr[nt]);
        }
    }
#pragma unroll
    for (int mt = 0; mt < 2; mt++) {
        int r0 = row0 + wm * 32 + mt * 16 + g;
#pragma unroll
        for (int half = 0; half < 2; half++) {
            int grr = r0 + half * 8;
            if (grr < m) {
                int tk = g_tok[e * NN + grr];
                float wgt = g_twt[e * NN + grr];
                float* orow = out + (size_t)tk * CC + cb;
#pragma unroll
                for (int nt = 0; nt < 4; nt++) {
                    int c = wn * 32 + nt * 8 + t * 2;
                    atomicAdd(&orow[c],     wgt * acc[mt][nt][half * 2]);
                    atomicAdd(&orow[c + 1], wgt * acc[mt][nt][half * 2 + 1]);
                }
            }
        }
    }
}

// ---------------- flash attention, split-KV (CHUNK=512) --------------------
#define TQ 64
#define TK 32
#define QPAD 129
#define KTPAD 36
#define SPAD 33

__global__ void __launch_bounds__(256) attn_kernel() {
    extern __shared__ float sm[];
    float* Qs = sm;                      // [TQ][QPAD]
    float* Kt = Qs + TQ * QPAD;          // [HH][KTPAD]
    float* Vs = Kt + HH * KTPAD;         // [TK][HH]
    float* Ss = Vs + TK * HH;            // [TQ][SPAD]
    float* mrow = Ss + TQ * SPAD;
    float* lrow = mrow + TQ;
    float* crow = lrow + TQ;

    int b = blockIdx.y;
    int wrk = blockIdx.x;
    int qt = 0;
    while (wrk >= (qt >> 3) + 1) { wrk -= (qt >> 3) + 1; qt++; }
    int ch = wrk;
    int q0 = qt * TQ;
    int kv0 = ch * 512;
    int kv1 = min(kv0 + 512, q0 + TQ);
    int tid = threadIdx.x;
    const float scale = 0.08838834764831845f;

    size_t qbase = ((size_t)(b * TT + q0)) * HH;
    for (int idx = tid; idx < TQ * HH; idx += 256) {
        int r = idx >> 7, h = idx & 127;
        Qs[r * QPAD + h] = g_q[qbase + idx];
    }
    if (tid < TQ) { mrow[tid] = NEGINF; lrow[tid] = 0.f; }

    int tm = tid >> 4, tn = tid & 15;
    float oacc[4][8];
#pragma unroll
    for (int i = 0; i < 4; i++)
#pragma unroll
        for (int j = 0; j < 8; j++) oacc[i][j] = 0.f;

    int tr = tid >> 3, tc = tid & 7;
    int ntiles = (kv1 - kv0) >> 5;

    for (int tix = 0; tix < ntiles; tix++) {
        int j0 = kv0 + tix * TK;
        size_t kbase = ((size_t)(b * TT + j0)) * HH;
        __syncthreads();
        for (int idx = tid; idx < TK * HH; idx += 256) {
            int r = idx >> 7, h = idx & 127;
            Kt[h * KTPAD + r] = g_k[kbase + idx];
        }
        for (int idx = tid; idx < TK * HH / 4; idx += 256)
            reinterpret_cast<float4*>(Vs)[idx] =
                reinterpret_cast<const float4*>(g_v + kbase)[idx];
        __syncthreads();
        {
            float s[2][4];
#pragma unroll
            for (int i = 0; i < 2; i++)
#pragma unroll
                for (int j = 0; j < 4; j++) s[i][j] = 0.f;
            for (int h = 0; h < HH; h++) {
                float qa = Qs[(tr * 2) * QPAD + h];
                float qb = Qs[(tr * 2 + 1) * QPAD + h];
                const float* kp = &Kt[h * KTPAD + tc * 4];
                float k0 = kp[0], k1 = kp[1], k2 = kp[2], k3 = kp[3];
                s[0][0] += qa * k0; s[0][1] += qa * k1; s[0][2] += qa * k2; s[0][3] += qa * k3;
                s[1][0] += qb * k0; s[1][1] += qb * k1; s[1][2] += qb * k2; s[1][3] += qb * k3;
            }
#pragma unroll
            for (int i = 0; i < 2; i++) {
                int qi = q0 + tr * 2 + i;
#pragma unroll
                for (int j = 0; j < 4; j++) {
                    int ki = j0 + tc * 4 + j;
                    Ss[(tr * 2 + i) * SPAD + tc * 4 + j] =
                        (ki <= qi) ? s[i][j] * scale : NEGINF;
                }
            }
        }
        __syncthreads();
        if (tid < TQ) {
            int r = tid;
            float mold = mrow[r];
            float tmax = NEGINF;
#pragma unroll
            for (int c = 0; c < TK; c++) tmax = fmaxf(tmax, Ss[r * SPAD + c]);
            float mnew = fmaxf(mold, tmax);
            float corr = __expf(mold - mnew);
            float sum = 0.f;
#pragma unroll
            for (int c = 0; c < TK; c++) {
                float pv = __expf(Ss[r * SPAD + c] - mnew);
                Ss[r * SPAD + c] = pv;
                sum += pv;
            }
            lrow[r] = lrow[r] * corr + sum;
            mrow[r] = mnew;
            crow[r] = corr;
        }
        __syncthreads();
#pragma unroll
        for (int i = 0; i < 4; i++) {
            float cr = crow[tm * 4 + i];
#pragma unroll
            for (int j = 0; j < 8; j++) oacc[i][j] *= cr;
        }
        for (int jj = 0; jj < TK; jj++) {
            float4 v0 = *reinterpret_cast<const float4*>(&Vs[jj * HH + tn * 8]);
            float4 v1 = *reinterpret_cast<const float4*>(&Vs[jj * HH + tn * 8 + 4]);
#pragma unroll
            for (int i = 0; i < 4; i++) {
                float pv = Ss[(tm * 4 + i) * SPAD + jj];
                oacc[i][0] += pv * v0.x; oacc[i][1] += pv * v0.y;
                oacc[i][2] += pv * v0.z; oacc[i][3] += pv * v0.w;
                oacc[i][4] += pv * v1.x; oacc[i][5] += pv * v1.y;
                oacc[i][6] += pv * v1.z; oacc[i][7] += pv * v1.w;
            }
        }
    }
    int base = ((b * NQT + qt) * 4 + ch) * TQ;
#pragma unroll
    for (int i = 0; i < 4; i++) {
        int r = tm * 4 + i;
        float* orow = g_pO + (size_t)(base + r) * HH + tn * 8;
        *reinterpret_cast<float4*>(orow) =
            make_float4(oacc[i][0], oacc[i][1], oacc[i][2], oacc[i][3]);
        *reinterpret_cast<float4*>(orow + 4) =
            make_float4(oacc[i][4], oacc[i][5], oacc[i][6], oacc[i][7]);
    }
    if (tid < TQ) { g_pm[base + tid] = mrow[tid]; g_pl[base + tid] = lrow[tid]; }
}

__global__ void __launch_bounds__(256) attn_combine_kernel() {
    int qt = blockIdx.x, b = blockIdx.y;
    int nch = (qt >> 3) + 1;
    int base = (b * NQT + qt) * 4 * TQ;
    int q0 = qt * TQ;
    for (int idx = threadIdx.x; idx < TQ * HH; idx += 256) {
        int r = idx >> 7, h = idx & 127;
        float mstar = NEGINF;
        for (int i = 0; i < nch; i++)
            mstar = fmaxf(mstar, g_pm[base + i * TQ + r]);
        float l = 0.f, o = 0.f;
        for (int i = 0; i < nch; i++) {
            float sc = __expf(g_pm[base + i * TQ + r] - mstar);
            l += sc * g_pl[base + i * TQ + r];
            o += sc * g_pO[(size_t)(base + i * TQ + r) * HH + h];
        }
        g_attn[((size_t)(b * TT + q0 + r)) * HH + h] = o / l;
    }
}

// ---------------- launch ---------------------------------------------------
extern "C" void kernel_launch(void* const* d_in, const int* in_sizes, int n_in,
                              void* d_out, int out_size) {
    const float* x   = (const float*)d_in[0];
    const float* sim = (const float*)d_in[1];
    const float* gts = (const float*)d_in[2];
    const float* qp  = (const float*)d_in[3];
    const float* kp  = (const float*)d_in[4];
    const float* vp  = (const float*)d_in[5];
    const float* op  = (const float*)d_in[6];
    const int* minexp = (const int*)d_in[7];
    float* out = (float*)d_out;

    const int attn_smem =
        (TQ * QPAD + HH * KTPAD + TK * HH + TQ * SPAD + 3 * TQ) * (int)sizeof(float);
    cudaFuncSetAttribute((const void*)attn_kernel,
                         cudaFuncAttributeMaxDynamicSharedMemorySize, attn_smem);

    zero4_kernel<<<4096, 256>>>((float4*)out, (NN * CC) / 4);
    zero_scratch_kernel<<<2048, 256>>>();
    colnorm_kernel<<<1, 256>>>(sim);
    logits_kernel<<<NN / 64, 256>>>(x, sim);
    select_kernel<<<NN / 8, 256>>>(gts, minexp);

    qkv_mma_kernel<<<dim3(NN / 64, 3, EE), 256>>>(x, qp, kp, vp);

    attn_kernel<<<dim3(80, BB), 256, attn_smem>>>();
    attn_combine_kernel<<<dim3(NQT, BB), 256>>>();

    oproj_mma_kernel<<<dim3(NN / 64, CC / 128, EE), 256>>>(op, out);
}

// round 5
// speedup vs baseline: 2.8655x; 1.0127x over previous
#include <cuda_runtime.h>
#include <math.h>

#define BB 4
#define TT 2048
#define CC 2048
#define HH 128
#define EE 16
#define NN (BB * TT)   // 8192 tokens
#define NQT (TT / 64)  // 32 q-tiles per batch
#define NEGINF (__int_as_float(0xff800000u))

// ---------------- scratch (device globals; no allocation allowed) ----------
__device__ float g_q[NN * HH];
__device__ float g_k[NN * HH];
__device__ float g_v[NN * HH];
__device__ float g_attn[NN * HH];
__device__ float g_invsnorm[EE];
__device__ int   g_cnt[EE];
__device__ int   g_tok[EE * NN];
__device__ float g_twt[EE * NN];
__device__ float g_logp[4 * NN * EE];   // split-K logit partials
__device__ float g_xxp[4 * NN];         // split-K |x|^2 partials
// attention split-KV partials: [B][qt][chunk<=4][64 rows][128]
__device__ float g_pO[BB * NQT * 4 * 64 * HH];
__device__ float g_pm[BB * NQT * 4 * 64];
__device__ float g_pl[BB * NQT * 4 * 64];

// ---------------- helpers ---------------------------------------------------
__device__ __forceinline__ unsigned f2tf(float f) {
    unsigned r;
    asm("cvt.rna.tf32.f32 %0, %1;" : "=r"(r) : "f"(f));
    return r;
}
__device__ __forceinline__ void mma_tf32(float* d, const unsigned* a, const unsigned* b) {
    asm volatile(
        "mma.sync.aligned.m16n8k8.row.col.f32.tf32.tf32.f32 "
        "{%0,%1,%2,%3},{%4,%5,%6,%7},{%8,%9},{%0,%1,%2,%3};"
        : "+f"(d[0]), "+f"(d[1]), "+f"(d[2]), "+f"(d[3])
        : "r"(a[0]), "r"(a[1]), "r"(a[2]), "r"(a[3]), "r"(b[0]), "r"(b[1]));
}

// ---------------- zero kernels --------------------------------------------
__global__ void zero4_kernel(float4* p, int n4) {
    int i = blockIdx.x * blockDim.x + threadIdx.x;
    int stride = gridDim.x * blockDim.x;
    float4 z = make_float4(0.f, 0.f, 0.f, 0.f);
    for (; i < n4; i += stride) p[i] = z;
}
__global__ void zero_scratch_kernel() {
    int i = blockIdx.x * blockDim.x + threadIdx.x;
    int stride = gridDim.x * blockDim.x;
    for (int j = i; j < NN * HH; j += stride) {
        g_q[j] = 0.f; g_k[j] = 0.f; g_v[j] = 0.f;
    }
    if (i < EE) g_cnt[i] = 0;
}

// ---------------- sim_matrix column inverse norms -------------------------
__global__ void colnorm_kernel(const float* __restrict__ sim) {
    int tid = threadIdx.x;
    float acc[EE];
#pragma unroll
    for (int e = 0; e < EE; e++) acc[e] = 0.f;
    for (int c = tid; c < CC; c += 256) {
        float sv[EE];
        const float4* row = reinterpret_cast<const float4*>(sim + (size_t)c * EE);
#pragma unroll
        for (int q = 0; q < 4; q++) *reinterpret_cast<float4*>(&sv[q * 4]) = row[q];
#pragma unroll
        for (int e = 0; e < EE; e++) acc[e] += sv[e] * sv[e];
    }
#pragma unroll
    for (int off = 16; off; off >>= 1)
#pragma unroll
        for (int e = 0; e < EE; e++)
            acc[e] += __shfl_xor_sync(0xffffffffu, acc[e], off);
    __shared__ float ws[8][EE];
    if ((tid & 31) == 0)
#pragma unroll
        for (int e = 0; e < EE; e++) ws[tid >> 5][e] = acc[e];
    __syncthreads();
    if (tid < EE) {
        float s = 0.f;
#pragma unroll
        for (int w = 0; w < 8; w++) s += ws[w][tid];
        g_invsnorm[tid] = 1.f / fmaxf(sqrtf(s), 1e-12f);
    }
}

// ---------------- logits: split-K x4, 64 tokens/block ----------------------
__global__ void __launch_bounds__(256) logits_kernel(const float* __restrict__ x,
                                                     const float* __restrict__ sim) {
    __shared__ float Xs[64][132];
    __shared__ float Ss[128][16];
    int n0 = blockIdx.x * 64;
    int part = blockIdx.y;          // K-quarter: columns [part*512, part*512+512)
    int tid = threadIdx.x;
    int tok = tid >> 2;
    int eg = tid & 3;
    float acc[4] = {0.f, 0.f, 0.f, 0.f};
    float xx = 0.f;
    int cbeg = part * 512;
    for (int c0 = cbeg; c0 < cbeg + 512; c0 += 128) {
        __syncthreads();
        for (int i = tid; i < 512; i += 256)
            reinterpret_cast<float4*>(&Ss[0][0])[i] =
                reinterpret_cast<const float4*>(sim + (size_t)c0 * EE)[i];
        for (int i = tid; i < 2048; i += 256) {
            int r = i >> 5, k4 = i & 31;
            *reinterpret_cast<float4*>(&Xs[r][k4 * 4]) =
                *reinterpret_cast<const float4*>(x + (size_t)(n0 + r) * CC + c0 + k4 * 4);
        }
        __syncthreads();
#pragma unroll 4
        for (int k = 0; k < 128; k++) {
            float xv = Xs[tok][k];
            float4 sv = *reinterpret_cast<const float4*>(&Ss[k][eg * 4]);
            acc[0] += xv * sv.x; acc[1] += xv * sv.y;
            acc[2] += xv * sv.z; acc[3] += xv * sv.w;
            if (eg == 0) xx += xv * xv;
        }
    }
    int n = n0 + tok;
    *reinterpret_cast<float4*>(&g_logp[((size_t)part * NN + n) * EE + eg * 4]) =
        make_float4(acc[0], acc[1], acc[2], acc[3]);
    if (eg == 0) g_xxp[part * NN + n] = xx;
}

// ---------------- selection: warp per token -------------------------------
__global__ void __launch_bounds__(256) select_kernel(const float* __restrict__ gates,
                                                     const int* __restrict__ min_experts_p) {
    int n = blockIdx.x * 8 + (threadIdx.x >> 5);
    int lane = threadIdx.x & 31;
    bool isE = (lane < EE);
    // deterministic fixed-order partial sums
    float xx = ((g_xxp[n] + g_xxp[NN + n]) + g_xxp[2 * NN + n]) + g_xxp[3 * NN + n];
    float invx = 1.f / fmaxf(sqrtf(xx), 1e-12f);
    float logit = NEGINF;
    if (isE) {
        float dot = ((g_logp[(size_t)n * EE + lane] +
                      g_logp[((size_t)NN + n) * EE + lane]) +
                     g_logp[((size_t)2 * NN + n) * EE + lane]) +
                    g_logp[((size_t)3 * NN + n) * EE + lane];
        float sig = 1.f / (1.f + __expf(-gates[lane]));
        logit = dot * invx * g_invsnorm[lane] - sig;
    }
    float gated = fmaxf(logit, 0.f);
    bool sel = isE && (logit > 0.f);
    unsigned act = __ballot_sync(0xffffffffu, sel);
    if (act == 0u) {
        int kreq = *min_experts_p;
        kreq = max(1, min(kreq, EE));
        bool chosen = false;
        for (int it = 0; it < kreq; it++) {
            float cand = (isE && !chosen) ? logit : NEGINF;
            float mv = cand;
#pragma unroll
            for (int off = 16; off; off >>= 1)
                mv = fmaxf(mv, __shfl_xor_sync(0xffffffffu, mv, off));
            unsigned bal = __ballot_sync(0xffffffffu, (cand == mv) && (mv != NEGINF));
            int ln = __ffs(bal) - 1;
            if (lane == ln) chosen = true;
        }
        sel = chosen;
    }
    float ml = sel ? gated : NEGINF;
    float mv = ml;
#pragma unroll
    for (int off = 16; off; off >>= 1)
        mv = fmaxf(mv, __shfl_xor_sync(0xffffffffu, mv, off));
    float p = sel ? __expf(gated - mv) : 0.f;
    float sum = p;
#pragma unroll
    for (int off = 16; off; off >>= 1)
        sum += __shfl_xor_sync(0xffffffffu, sum, off);
    if (sel) {
        float w = p / sum;
        int pos = atomicAdd(&g_cnt[lane], 1);
        g_tok[lane * NN + pos] = n;
        g_twt[lane * NN + pos] = w;
    }
}

// ---------------- fused QKV grouped GEMM (tf32 mma, sw-pipelined) ----------
// grid (NN/64, 3, EE); block 256. Tile 64x128, K=2048 in chunks of 32.
__global__ void __launch_bounds__(256)
qkv_mma_kernel(const float* __restrict__ x, const float* __restrict__ qp,
               const float* __restrict__ kp, const float* __restrict__ vp) {
    const int e = blockIdx.z;
    const int m = g_cnt[e];
    const int row0 = blockIdx.x * 64;
    if (row0 >= m) return;
    const int p = blockIdx.y;
    const float* B = ((p == 0) ? qp : (p == 1) ? kp : vp) + (size_t)e * CC * HH;
    float* Out = (p == 0) ? g_q : (p == 1) ? g_k : g_v;

    __shared__ unsigned As[64 * 36];   // [m][k] stride 36
    __shared__ unsigned Bs[32 * 136];  // [k][n] stride 136

    const int tid = threadIdx.x, lane = tid & 31, w = tid >> 5;
    const int wm = w & 1, wn = w >> 1;
    const int g = lane >> 2, t = lane & 3;

    float acc[2][4][4];
#pragma unroll
    for (int mt = 0; mt < 2; mt++)
#pragma unroll
        for (int nt = 0; nt < 4; nt++)
#pragma unroll
            for (int i = 0; i < 4; i++) acc[mt][nt][i] = 0.f;

    const int ar = tid >> 2, akb = (tid & 3) * 8;
    int gr = row0 + ar;
    int tok = g_tok[e * NN + ((gr < m) ? gr : (m - 1))];
    const float* aptr = x + (size_t)tok * CC + akb;
    const int br = tid >> 3, bnb = (tid & 7) * 16;
    const float* bptr = B + (size_t)br * HH + bnb;

    // prologue: prefetch first chunk
    float4 av0 = *reinterpret_cast<const float4*>(aptr);
    float4 av1 = *reinterpret_cast<const float4*>(aptr + 4);
    float4 bv[4];
#pragma unroll
    for (int j = 0; j < 4; j++)
        bv[j] = *reinterpret_cast<const float4*>(bptr + j * 4);

    for (int k0 = 0; k0 < CC; k0 += 32) {
        __syncthreads();
        {
            uint4 u0 = make_uint4(f2tf(av0.x), f2tf(av0.y), f2tf(av0.z), f2tf(av0.w));
            uint4 u1 = make_uint4(f2tf(av1.x), f2tf(av1.y), f2tf(av1.z), f2tf(av1.w));
            *reinterpret_cast<uint4*>(&As[ar * 36 + akb]) = u0;
            *reinterpret_cast<uint4*>(&As[ar * 36 + akb + 4]) = u1;
#pragma unroll
            for (int j = 0; j < 4; j++) {
                uint4 ub = make_uint4(f2tf(bv[j].x), f2tf(bv[j].y), f2tf(bv[j].z), f2tf(bv[j].w));
                *reinterpret_cast<uint4*>(&Bs[br * 136 + bnb + j * 4]) = ub;
            }
        }
        __syncthreads();
        // prefetch next chunk (overlaps with MMA below)
        if (k0 + 32 < CC) {
            av0 = *reinterpret_cast<const float4*>(aptr + k0 + 32);
            av1 = *reinterpret_cast<const float4*>(aptr + k0 + 36);
#pragma unroll
            for (int j = 0; j < 4; j++)
                bv[j] = *reinterpret_cast<const float4*>(bptr + (size_t)(k0 + 32) * HH + j * 4);
        }
#pragma unroll
        for (int kk = 0; kk < 4; kk++) {
            unsigned afr[2][4], bfr[4][2];
#pragma unroll
            for (int mt = 0; mt < 2; mt++) {
                int ab = (wm * 32 + mt * 16 + g) * 36 + kk * 8 + t;
                afr[mt][0] = As[ab];       afr[mt][1] = As[ab + 288];
                afr[mt][2] = As[ab + 4];   afr[mt][3] = As[ab + 292];
            }
#pragma unroll
            for (int nt = 0; nt < 4; nt++) {
                int col = wn * 32 + nt * 8 + g;
                int bb = (kk * 8 + t) * 136 + col;
                bfr[nt][0] = Bs[bb];
                bfr[nt][1] = Bs[bb + 544];
            }
#pragma unroll
            for (int mt = 0; mt < 2; mt++)
#pragma unroll
                for (int nt = 0; nt < 4; nt++) mma_tf32(acc[mt][nt], afr[mt], bfr[nt]);
        }
    }
#pragma unroll
    for (int mt = 0; mt < 2; mt++) {
        int r0 = row0 + wm * 32 + mt * 16 + g;
#pragma unroll
        for (int half = 0; half < 2; half++) {
            int grr = r0 + half * 8;
            if (grr < m) {
                int tk = g_tok[e * NN + grr];
                float wgt = g_twt[e * NN + grr];
                float* orow = Out + (size_t)tk * HH;
#pragma unroll
                for (int nt = 0; nt < 4; nt++) {
                    int c = wn * 32 + nt * 8 + t * 2;
                    atomicAdd(&orow[c],     wgt * acc[mt][nt][half * 2]);
                    atomicAdd(&orow[c + 1], wgt * acc[mt][nt][half * 2 + 1]);
                }
            }
        }
    }
}

// ---------------- o-proj grouped GEMM (tf32 mma, sw-pipelined) -------------
// grid (NN/64, CC/128, EE); K = HH = 128.
__global__ void __launch_bounds__(256)
oproj_mma_kernel(const float* __restrict__ op, float* __restrict__ out) {
    const int e = blockIdx.z;
    const int m = g_cnt[e];
    const int row0 = blockIdx.x * 64;
    if (row0 >= m) return;
    const int cb = blockIdx.y * 128;
    const float* B = op + (size_t)e * HH * CC + cb;

    __shared__ unsigned As[64 * 36];
    __shared__ unsigned Bs[32 * 136];

    const int tid = threadIdx.x, lane = tid & 31, w = tid >> 5;
    const int wm = w & 1, wn = w >> 1;
    const int g = lane >> 2, t = lane & 3;

    float acc[2][4][4];
#pragma unroll
    for (int mt = 0; mt < 2; mt++)
#pragma unroll
        for (int nt = 0; nt < 4; nt++)
#pragma unroll
            for (int i = 0; i < 4; i++) acc[mt][nt][i] = 0.f;

    const int ar = tid >> 2, akb = (tid & 3) * 8;
    int gr = row0 + ar;
    int tok = g_tok[e * NN + ((gr < m) ? gr : (m - 1))];
    const float* aptr = g_attn + (size_t)tok * HH + akb;
    const int br = tid >> 3, bnb = (tid & 7) * 16;
    const float* bptr = B + (size_t)br * CC + bnb;

    float4 av0 = *reinterpret_cast<const float4*>(aptr);
    float4 av1 = *reinterpret_cast<const float4*>(aptr + 4);
    float4 bv[4];
#pragma unroll
    for (int j = 0; j < 4; j++)
        bv[j] = *reinterpret_cast<const float4*>(bptr + j * 4);

    for (int k0 = 0; k0 < HH; k0 += 32) {
        __syncthreads();
        {
            uint4 u0 = make_uint4(f2tf(av0.x), f2tf(av0.y), f2tf(av0.z), f2tf(av0.w));
            uint4 u1 = make_uint4(f2tf(av1.x), f2tf(av1.y), f2tf(av1.z), f2tf(av1.w));
            *reinterpret_cast<uint4*>(&As[ar * 36 + akb]) = u0;
            *reinterpret_cast<uint4*>(&As[ar * 36 + akb + 4]) = u1;
#pragma unroll
            for (int j = 0; j < 4; j++) {
                uint4 ub = make_uint4(f2tf(bv[j].x), f2tf(bv[j].y), f2tf(bv[j].z), f2tf(bv[j].w));
                *reinterpret_cast<uint4*>(&Bs[br * 136 + bnb + j * 4]) = ub;
            }
        }
        __syncthreads();
        if (k0 + 32 < HH) {
            av0 = *reinterpret_cast<const float4*>(aptr + k0 + 32);
            av1 = *reinterpret_cast<const float4*>(aptr + k0 + 36);
#pragma unroll
            for (int j = 0; j < 4; j++)
                bv[j] = *reinterpret_cast<const float4*>(bptr + (size_t)(k0 + 32) * CC + j * 4);
        }
#pragma unroll
        for (int kk = 0; kk < 4; kk++) {
            unsigned afr[2][4], bfr[4][2];
#pragma unroll
            for (int mt = 0; mt < 2; mt++) {
                int ab = (wm * 32 + mt * 16 + g) * 36 + kk * 8 + t;
                afr[mt][0] = As[ab];       afr[mt][1] = As[ab + 288];
                afr[mt][2] = As[ab + 4];   afr[mt][3] = As[ab + 292];
            }
#pragma unroll
            for (int nt = 0; nt < 4; nt++) {
                int col = wn * 32 + nt * 8 + g;
                int bb = (kk * 8 + t) * 136 + col;
                bfr[nt][0] = Bs[bb];
                bfr[nt][1] = Bs[bb + 544];
            }
#pragma unroll
            for (int mt = 0; mt < 2; mt++)
#pragma unroll
                for (int nt = 0; nt < 4; nt++) mma_tf32(acc[mt][nt], afr[mt], bfr[nt]);
        }
    }
#pragma unroll
    for (int mt = 0; mt < 2; mt++) {
        int r0 = row0 + wm * 32 + mt * 16 + g;
#pragma unroll
        for (int half = 0; half < 2; half++) {
            int grr = r0 + half * 8;
            if (grr < m) {
                int tk = g_tok[e * NN + grr];
                float wgt = g_twt[e * NN + grr];
                float* orow = out + (size_t)tk * CC + cb;
#pragma unroll
                for (int nt = 0; nt < 4; nt++) {
                    int c = wn * 32 + nt * 8 + t * 2;
                    atomicAdd(&orow[c],     wgt * acc[mt][nt][half * 2]);
                    atomicAdd(&orow[c + 1], wgt * acc[mt][nt][half * 2 + 1]);
                }
            }
        }
    }
}

// ---------------- flash attention, split-KV (CHUNK=512) --------------------
#define TQ 64
#define TK 32
#define QPAD 129
#define KTPAD 36
#define SPAD 33

__global__ void __launch_bounds__(256) attn_kernel() {
    extern __shared__ float sm[];
    float* Qs = sm;                      // [TQ][QPAD]
    float* Kt = Qs + TQ * QPAD;          // [HH][KTPAD]
    float* Vs = Kt + HH * KTPAD;         // [TK][HH]
    float* Ss = Vs + TK * HH;            // [TQ][SPAD]
    float* mrow = Ss + TQ * SPAD;
    float* lrow = mrow + TQ;
    float* crow = lrow + TQ;

    int b = blockIdx.y;
    int wrk = blockIdx.x;
    int qt = 0;
    while (wrk >= (qt >> 3) + 1) { wrk -= (qt >> 3) + 1; qt++; }
    int ch = wrk;
    int q0 = qt * TQ;
    int kv0 = ch * 512;
    int kv1 = min(kv0 + 512, q0 + TQ);
    int tid = threadIdx.x;
    const float scale = 0.08838834764831845f;

    size_t qbase = ((size_t)(b * TT + q0)) * HH;
    for (int idx = tid; idx < TQ * HH; idx += 256) {
        int r = idx >> 7, h = idx & 127;
        Qs[r * QPAD + h] = g_q[qbase + idx];
    }
    if (tid < TQ) { mrow[tid] = NEGINF; lrow[tid] = 0.f; }

    int tm = tid >> 4, tn = tid & 15;
    float oacc[4][8];
#pragma unroll
    for (int i = 0; i < 4; i++)
#pragma unroll
        for (int j = 0; j < 8; j++) oacc[i][j] = 0.f;

    int tr = tid >> 3, tc = tid & 7;
    int ntiles = (kv1 - kv0) >> 5;

    for (int tix = 0; tix < ntiles; tix++) {
        int j0 = kv0 + tix * TK;
        size_t kbase = ((size_t)(b * TT + j0)) * HH;
        __syncthreads();
        for (int idx = tid; idx < TK * HH; idx += 256) {
            int r = idx >> 7, h = idx & 127;
            Kt[h * KTPAD + r] = g_k[kbase + idx];
        }
        for (int idx = tid; idx < TK * HH / 4; idx += 256)
            reinterpret_cast<float4*>(Vs)[idx] =
                reinterpret_cast<const float4*>(g_v + kbase)[idx];
        __syncthreads();
        {
            float s[2][4];
#pragma unroll
            for (int i = 0; i < 2; i++)
#pragma unroll
                for (int j = 0; j < 4; j++) s[i][j] = 0.f;
            for (int h = 0; h < HH; h++) {
                float qa = Qs[(tr * 2) * QPAD + h];
                float qb = Qs[(tr * 2 + 1) * QPAD + h];
                const float* kp = &Kt[h * KTPAD + tc * 4];
                float k0 = kp[0], k1 = kp[1], k2 = kp[2], k3 = kp[3];
                s[0][0] += qa * k0; s[0][1] += qa * k1; s[0][2] += qa * k2; s[0][3] += qa * k3;
                s[1][0] += qb * k0; s[1][1] += qb * k1; s[1][2] += qb * k2; s[1][3] += qb * k3;
            }
#pragma unroll
            for (int i = 0; i < 2; i++) {
                int qi = q0 + tr * 2 + i;
#pragma unroll
                for (int j = 0; j < 4; j++) {
                    int ki = j0 + tc * 4 + j;
                    Ss[(tr * 2 + i) * SPAD + tc * 4 + j] =
                        (ki <= qi) ? s[i][j] * scale : NEGINF;
                }
            }
        }
        __syncthreads();
        if (tid < TQ) {
            int r = tid;
            float mold = mrow[r];
            float tmax = NEGINF;
#pragma unroll
            for (int c = 0; c < TK; c++) tmax = fmaxf(tmax, Ss[r * SPAD + c]);
            float mnew = fmaxf(mold, tmax);
            float corr = __expf(mold - mnew);
            float sum = 0.f;
#pragma unroll
            for (int c = 0; c < TK; c++) {
                float pv = __expf(Ss[r * SPAD + c] - mnew);
                Ss[r * SPAD + c] = pv;
                sum += pv;
            }
            lrow[r] = lrow[r] * corr + sum;
            mrow[r] = mnew;
            crow[r] = corr;
        }
        __syncthreads();
#pragma unroll
        for (int i = 0; i < 4; i++) {
            float cr = crow[tm * 4 + i];
#pragma unroll
            for (int j = 0; j < 8; j++) oacc[i][j] *= cr;
        }
        for (int jj = 0; jj < TK; jj++) {
            float4 v0 = *reinterpret_cast<const float4*>(&Vs[jj * HH + tn * 8]);
            float4 v1 = *reinterpret_cast<const float4*>(&Vs[jj * HH + tn * 8 + 4]);
#pragma unroll
            for (int i = 0; i < 4; i++) {
                float pv = Ss[(tm * 4 + i) * SPAD + jj];
                oacc[i][0] += pv * v0.x; oacc[i][1] += pv * v0.y;
                oacc[i][2] += pv * v0.z; oacc[i][3] += pv * v0.w;
                oacc[i][4] += pv * v1.x; oacc[i][5] += pv * v1.y;
                oacc[i][6] += pv * v1.z; oacc[i][7] += pv * v1.w;
            }
        }
    }
    int base = ((b * NQT + qt) * 4 + ch) * TQ;
#pragma unroll
    for (int i = 0; i < 4; i++) {
        int r = tm * 4 + i;
        float* orow = g_pO + (size_t)(base + r) * HH + tn * 8;
        *reinterpret_cast<float4*>(orow) =
            make_float4(oacc[i][0], oacc[i][1], oacc[i][2], oacc[i][3]);
        *reinterpret_cast<float4*>(orow + 4) =
            make_float4(oacc[i][4], oacc[i][5], oacc[i][6], oacc[i][7]);
    }
    if (tid < TQ) { g_pm[base + tid] = mrow[tid]; g_pl[base + tid] = lrow[tid]; }
}

__global__ void __launch_bounds__(256) attn_combine_kernel() {
    int qt = blockIdx.x, b = blockIdx.y;
    int nch = (qt >> 3) + 1;
    int base = (b * NQT + qt) * 4 * TQ;
    int q0 = qt * TQ;
    for (int idx = threadIdx.x; idx < TQ * HH; idx += 256) {
        int r = idx >> 7, h = idx & 127;
        float mstar = NEGINF;
        for (int i = 0; i < nch; i++)
            mstar = fmaxf(mstar, g_pm[base + i * TQ + r]);
        float l = 0.f, o = 0.f;
        for (int i = 0; i < nch; i++) {
            float sc = __expf(g_pm[base + i * TQ + r] - mstar);
            l += sc * g_pl[base + i * TQ + r];
            o += sc * g_pO[(size_t)(base + i * TQ + r) * HH + h];
        }
        g_attn[((size_t)(b * TT + q0 + r)) * HH + h] = o / l;
    }
}

// ---------------- launch ---------------------------------------------------
extern "C" void kernel_launch(void* const* d_in, const int* in_sizes, int n_in,
                              void* d_out, int out_size) {
    const float* x   = (const float*)d_in[0];
    const float* sim = (const float*)d_in[1];
    const float* gts = (const float*)d_in[2];
    const float* qp  = (const float*)d_in[3];
    const float* kp  = (const float*)d_in[4];
    const float* vp  = (const float*)d_in[5];
    const float* op  = (const float*)d_in[6];
    const int* minexp = (const int*)d_in[7];
    float* out = (float*)d_out;

    const int attn_smem =
        (TQ * QPAD + HH * KTPAD + TK * HH + TQ * SPAD + 3 * TQ) * (int)sizeof(float);
    cudaFuncSetAttribute((const void*)attn_kernel,
                         cudaFuncAttributeMaxDynamicSharedMemorySize, attn_smem);

    zero4_kernel<<<4096, 256>>>((float4*)out, (NN * CC) / 4);
    zero_scratch_kernel<<<2048, 256>>>();
    colnorm_kernel<<<1, 256>>>(sim);
    logits_kernel<<<dim3(NN / 64, 4), 256>>>(x, sim);
    select_kernel<<<NN / 8, 256>>>(gts, minexp);

    qkv_mma_kernel<<<dim3(NN / 64, 3, EE), 256>>>(x, qp, kp, vp);

    attn_kernel<<<dim3(80, BB), 256, attn_smem>>>();
    attn_combine_kernel<<<dim3(NQT, BB), 256>>>();

    oproj_mma_kernel<<<dim3(NN / 64, CC / 128, EE), 256>>>(op, out);
}

// round 7
// speedup vs baseline: 3.0972x; 1.0809x over previous
#include <cuda_runtime.h>
#include <math.h>

#define BB 4
#define TT 2048
#define CC 2048
#define HH 128
#define EE 16
#define NN (BB * TT)   // 8192 tokens
#define NQT (TT / 64)  // 32 q-tiles per batch
#define NEGINF (__int_as_float(0xff800000u))

// ---------------- scratch (device globals; no allocation allowed) ----------
__device__ float g_q[NN * HH];
__device__ float g_k[NN * HH];
__device__ float g_v[NN * HH];
__device__ float g_attn[NN * HH];
__device__ float g_invsnorm[EE];
__device__ int   g_cnt[EE];
__device__ int   g_tok[EE * NN];
__device__ float g_twt[EE * NN];
__device__ float g_logp[8 * NN * EE];   // split-K logit partials
__device__ float g_xxp[8 * NN];         // split-K |x|^2 partials
// attention split-KV partials: [B][qt][chunk<=4][64 rows][128]
__device__ float g_pO[BB * NQT * 4 * 64 * HH];
__device__ float g_pm[BB * NQT * 4 * 64];
__device__ float g_pl[BB * NQT * 4 * 64];

// ---------------- helpers ---------------------------------------------------
__device__ __forceinline__ unsigned f2tf(float f) {
    unsigned r;
    asm("cvt.rna.tf32.f32 %0, %1;" : "=r"(r) : "f"(f));
    return r;
}
__device__ __forceinline__ void mma_tf32(float* d, const unsigned* a, const unsigned* b) {
    asm volatile(
        "mma.sync.aligned.m16n8k8.row.col.f32.tf32.tf32.f32 "
        "{%0,%1,%2,%3},{%4,%5,%6,%7},{%8,%9},{%0,%1,%2,%3};"
        : "+f"(d[0]), "+f"(d[1]), "+f"(d[2]), "+f"(d[3])
        : "r"(a[0]), "r"(a[1]), "r"(a[2]), "r"(a[3]), "r"(b[0]), "r"(b[1]));
}

// ---------------- zero kernels --------------------------------------------
__global__ void zero4_kernel(float4* p, int n4) {
    int i = blockIdx.x * blockDim.x + threadIdx.x;
    int stride = gridDim.x * blockDim.x;
    float4 z = make_float4(0.f, 0.f, 0.f, 0.f);
    for (; i < n4; i += stride) p[i] = z;
}
__global__ void zero_scratch_kernel() {
    int i = blockIdx.x * blockDim.x + threadIdx.x;
    int stride = gridDim.x * blockDim.x;
    for (int j = i; j < NN * HH; j += stride) {
        g_q[j] = 0.f; g_k[j] = 0.f; g_v[j] = 0.f;
    }
    if (i < EE) g_cnt[i] = 0;
}

// ---------------- sim_matrix column inverse norms -------------------------
__global__ void colnorm_kernel(const float* __restrict__ sim) {
    int tid = threadIdx.x;
    float acc[EE];
#pragma unroll
    for (int e = 0; e < EE; e++) acc[e] = 0.f;
    for (int c = tid; c < CC; c += 256) {
        float sv[EE];
        const float4* row = reinterpret_cast<const float4*>(sim + (size_t)c * EE);
#pragma unroll
        for (int q = 0; q < 4; q++) *reinterpret_cast<float4*>(&sv[q * 4]) = row[q];
#pragma unroll
        for (int e = 0; e < EE; e++) acc[e] += sv[e] * sv[e];
    }
#pragma unroll
    for (int off = 16; off; off >>= 1)
#pragma unroll
        for (int e = 0; e < EE; e++)
            acc[e] += __shfl_xor_sync(0xffffffffu, acc[e], off);
    __shared__ float ws[8][EE];
    if ((tid & 31) == 0)
#pragma unroll
        for (int e = 0; e < EE; e++) ws[tid >> 5][e] = acc[e];
    __syncthreads();
    if (tid < EE) {
        float s = 0.f;
#pragma unroll
        for (int w = 0; w < 8; w++) s += ws[w][tid];
        g_invsnorm[tid] = 1.f / fmaxf(sqrtf(s), 1e-12f);
    }
}

// ---------------- logits: split-K x8, 64 tokens/block ----------------------
__global__ void __launch_bounds__(256) logits_kernel(const float* __restrict__ x,
                                                     const float* __restrict__ sim) {
    __shared__ float Xs[64][132];
    __shared__ float Ss[128][16];
    int n0 = blockIdx.x * 64;
    int part = blockIdx.y;          // K-eighth: columns [part*256, part*256+256)
    int tid = threadIdx.x;
    int tok = tid >> 2;
    int eg = tid & 3;
    float acc[4] = {0.f, 0.f, 0.f, 0.f};
    float xx = 0.f;
    int cbeg = part * 256;
    for (int c0 = cbeg; c0 < cbeg + 256; c0 += 128) {
        __syncthreads();
        for (int i = tid; i < 512; i += 256)
            reinterpret_cast<float4*>(&Ss[0][0])[i] =
                reinterpret_cast<const float4*>(sim + (size_t)c0 * EE)[i];
        for (int i = tid; i < 2048; i += 256) {
            int r = i >> 5, k4 = i & 31;
            *reinterpret_cast<float4*>(&Xs[r][k4 * 4]) =
                *reinterpret_cast<const float4*>(x + (size_t)(n0 + r) * CC + c0 + k4 * 4);
        }
        __syncthreads();
#pragma unroll 4
        for (int k = 0; k < 128; k++) {
            float xv = Xs[tok][k];
            float4 sv = *reinterpret_cast<const float4*>(&Ss[k][eg * 4]);
            acc[0] += xv * sv.x; acc[1] += xv * sv.y;
            acc[2] += xv * sv.z; acc[3] += xv * sv.w;
            if (eg == 0) xx += xv * xv;
        }
    }
    int n = n0 + tok;
    *reinterpret_cast<float4*>(&g_logp[((size_t)part * NN + n) * EE + eg * 4]) =
        make_float4(acc[0], acc[1], acc[2], acc[3]);
    if (eg == 0) g_xxp[part * NN + n] = xx;
}

// ---------------- selection: warp per token -------------------------------
__global__ void __launch_bounds__(256) select_kernel(const float* __restrict__ gates,
                                                     const int* __restrict__ min_experts_p) {
    int n = blockIdx.x * 8 + (threadIdx.x >> 5);
    int lane = threadIdx.x & 31;
    bool isE = (lane < EE);
    // deterministic fixed-order partial sums
    float xx = 0.f;
#pragma unroll
    for (int p8 = 0; p8 < 8; p8++) xx += g_xxp[p8 * NN + n];
    float invx = 1.f / fmaxf(sqrtf(xx), 1e-12f);
    float logit = NEGINF;
    if (isE) {
        float dot = 0.f;
#pragma unroll
        for (int p8 = 0; p8 < 8; p8++)
            dot += g_logp[((size_t)p8 * NN + n) * EE + lane];
        float sig = 1.f / (1.f + __expf(-gates[lane]));
        logit = dot * invx * g_invsnorm[lane] - sig;
    }
    float gated = fmaxf(logit, 0.f);
    bool sel = isE && (logit > 0.f);
    unsigned act = __ballot_sync(0xffffffffu, sel);
    if (act == 0u) {
        int kreq = *min_experts_p;
        kreq = max(1, min(kreq, EE));
        bool chosen = false;
        for (int it = 0; it < kreq; it++) {
            float cand = (isE && !chosen) ? logit : NEGINF;
            float mv = cand;
#pragma unroll
            for (int off = 16; off; off >>= 1)
                mv = fmaxf(mv, __shfl_xor_sync(0xffffffffu, mv, off));
            unsigned bal = __ballot_sync(0xffffffffu, (cand == mv) && (mv != NEGINF));
            int ln = __ffs(bal) - 1;
            if (lane == ln) chosen = true;
        }
        sel = chosen;
    }
    float ml = sel ? gated : NEGINF;
    float mv = ml;
#pragma unroll
    for (int off = 16; off; off >>= 1)
        mv = fmaxf(mv, __shfl_xor_sync(0xffffffffu, mv, off));
    float p = sel ? __expf(gated - mv) : 0.f;
    float sum = p;
#pragma unroll
    for (int off = 16; off; off >>= 1)
        sum += __shfl_xor_sync(0xffffffffu, sum, off);
    if (sel) {
        float w = p / sum;
        int pos = atomicAdd(&g_cnt[lane], 1);
        g_tok[lane * NN + pos] = n;
        g_twt[lane * NN + pos] = w;
    }
}

// ---------------- fused QKV grouped GEMM (tf32 mma, sw-pipelined) ----------
// grid (NN/64, 3, EE); block 256. Tile 64x128, K=2048 in chunks of 32.
__global__ void __launch_bounds__(256)
qkv_mma_kernel(const float* __restrict__ x, const float* __restrict__ qp,
               const float* __restrict__ kp, const float* __restrict__ vp) {
    const int e = blockIdx.z;
    const int m = g_cnt[e];
    const int row0 = blockIdx.x * 64;
    if (row0 >= m) return;
    const int p = blockIdx.y;
    const float* B = ((p == 0) ? qp : (p == 1) ? kp : vp) + (size_t)e * CC * HH;
    float* Out = (p == 0) ? g_q : (p == 1) ? g_k : g_v;

    __shared__ unsigned As[64 * 36];   // [m][k] stride 36
    __shared__ unsigned Bs[32 * 136];  // [k][n] stride 136

    const int tid = threadIdx.x, lane = tid & 31, w = tid >> 5;
    const int wm = w & 1, wn = w >> 1;
    const int g = lane >> 2, t = lane & 3;

    float acc[2][4][4];
#pragma unroll
    for (int mt = 0; mt < 2; mt++)
#pragma unroll
        for (int nt = 0; nt < 4; nt++)
#pragma unroll
            for (int i = 0; i < 4; i++) acc[mt][nt][i] = 0.f;

    const int ar = tid >> 2, akb = (tid & 3) * 8;
    int gr = row0 + ar;
    int tok = g_tok[e * NN + ((gr < m) ? gr : (m - 1))];
    const float* aptr = x + (size_t)tok * CC + akb;
    const int br = tid >> 3, bnb = (tid & 7) * 16;
    const float* bptr = B + (size_t)br * HH + bnb;

    // prologue: prefetch first chunk
    float4 av0 = *reinterpret_cast<const float4*>(aptr);
    float4 av1 = *reinterpret_cast<const float4*>(aptr + 4);
    float4 bv[4];
#pragma unroll
    for (int j = 0; j < 4; j++)
        bv[j] = *reinterpret_cast<const float4*>(bptr + j * 4);

    for (int k0 = 0; k0 < CC; k0 += 32) {
        __syncthreads();
        {
            uint4 u0 = make_uint4(f2tf(av0.x), f2tf(av0.y), f2tf(av0.z), f2tf(av0.w));
            uint4 u1 = make_uint4(f2tf(av1.x), f2tf(av1.y), f2tf(av1.z), f2tf(av1.w));
            *reinterpret_cast<uint4*>(&As[ar * 36 + akb]) = u0;
            *reinterpret_cast<uint4*>(&As[ar * 36 + akb + 4]) = u1;
#pragma unroll
            for (int j = 0; j < 4; j++) {
                uint4 ub = make_uint4(f2tf(bv[j].x), f2tf(bv[j].y), f2tf(bv[j].z), f2tf(bv[j].w));
                *reinterpret_cast<uint4*>(&Bs[br * 136 + bnb + j * 4]) = ub;
            }
        }
        __syncthreads();
        // prefetch next chunk (overlaps with MMA below)
        if (k0 + 32 < CC) {
            av0 = *reinterpret_cast<const float4*>(aptr + k0 + 32);
            av1 = *reinterpret_cast<const float4*>(aptr + k0 + 36);
#pragma unroll
            for (int j = 0; j < 4; j++)
                bv[j] = *reinterpret_cast<const float4*>(bptr + (size_t)(k0 + 32) * HH + j * 4);
        }
#pragma unroll
        for (int kk = 0; kk < 4; kk++) {
            unsigned afr[2][4], bfr[4][2];
#pragma unroll
            for (int mt = 0; mt < 2; mt++) {
                int ab = (wm * 32 + mt * 16 + g) * 36 + kk * 8 + t;
                afr[mt][0] = As[ab];       afr[mt][1] = As[ab + 288];
                afr[mt][2] = As[ab + 4];   afr[mt][3] = As[ab + 292];
            }
#pragma unroll
            for (int nt = 0; nt < 4; nt++) {
                int col = wn * 32 + nt * 8 + g;
                int bb = (kk * 8 + t) * 136 + col;
                bfr[nt][0] = Bs[bb];
                bfr[nt][1] = Bs[bb + 544];
            }
#pragma unroll
            for (int mt = 0; mt < 2; mt++)
#pragma unroll
                for (int nt = 0; nt < 4; nt++) mma_tf32(acc[mt][nt], afr[mt], bfr[nt]);
        }
    }
#pragma unroll
    for (int mt = 0; mt < 2; mt++) {
        int r0 = row0 + wm * 32 + mt * 16 + g;
#pragma unroll
        for (int half = 0; half < 2; half++) {
            int grr = r0 + half * 8;
            if (grr < m) {
                int tk = g_tok[e * NN + grr];
                float wgt = g_twt[e * NN + grr];
                float* orow = Out + (size_t)tk * HH;
#pragma unroll
                for (int nt = 0; nt < 4; nt++) {
                    int c = wn * 32 + nt * 8 + t * 2;
                    atomicAdd(&orow[c],     wgt * acc[mt][nt][half * 2]);
                    atomicAdd(&orow[c + 1], wgt * acc[mt][nt][half * 2 + 1]);
                }
            }
        }
    }
}

// ---------------- o-proj grouped GEMM (tf32 mma, sw-pipelined) -------------
// grid (NN/64, CC/128, EE); K = HH = 128.
__global__ void __launch_bounds__(256)
oproj_mma_kernel(const float* __restrict__ op, float* __restrict__ out) {
    const int e = blockIdx.z;
    const int m = g_cnt[e];
    const int row0 = blockIdx.x * 64;
    if (row0 >= m) return;
    const int cb = blockIdx.y * 128;
    const float* B = op + (size_t)e * HH * CC + cb;

    __shared__ unsigned As[64 * 36];
    __shared__ unsigned Bs[32 * 136];

    const int tid = threadIdx.x, lane = tid & 31, w = tid >> 5;
    const int wm = w & 1, wn = w >> 1;
    const int g = lane >> 2, t = lane & 3;

    float acc[2][4][4];
#pragma unroll
    for (int mt = 0; mt < 2; mt++)
#pragma unroll
        for (int nt = 0; nt < 4; nt++)
#pragma unroll
            for (int i = 0; i < 4; i++) acc[mt][nt][i] = 0.f;

    const int ar = tid >> 2, akb = (tid & 3) * 8;
    int gr = row0 + ar;
    int tok = g_tok[e * NN + ((gr < m) ? gr : (m - 1))];
    const float* aptr = g_attn + (size_t)tok * HH + akb;
    const int br = tid >> 3, bnb = (tid & 7) * 16;
    const float* bptr = B + (size_t)br * CC + bnb;

    float4 av0 = *reinterpret_cast<const float4*>(aptr);
    float4 av1 = *reinterpret_cast<const float4*>(aptr + 4);
    float4 bv[4];
#pragma unroll
    for (int j = 0; j < 4; j++)
        bv[j] = *reinterpret_cast<const float4*>(bptr + j * 4);

    for (int k0 = 0; k0 < HH; k0 += 32) {
        __syncthreads();
        {
            uint4 u0 = make_uint4(f2tf(av0.x), f2tf(av0.y), f2tf(av0.z), f2tf(av0.w));
            uint4 u1 = make_uint4(f2tf(av1.x), f2tf(av1.y), f2tf(av1.z), f2tf(av1.w));
            *reinterpret_cast<uint4*>(&As[ar * 36 + akb]) = u0;
            *reinterpret_cast<uint4*>(&As[ar * 36 + akb + 4]) = u1;
#pragma unroll
            for (int j = 0; j < 4; j++) {
                uint4 ub = make_uint4(f2tf(bv[j].x), f2tf(bv[j].y), f2tf(bv[j].z), f2tf(bv[j].w));
                *reinterpret_cast<uint4*>(&Bs[br * 136 + bnb + j * 4]) = ub;
            }
        }
        __syncthreads();
        if (k0 + 32 < HH) {
            av0 = *reinterpret_cast<const float4*>(aptr + k0 + 32);
            av1 = *reinterpret_cast<const float4*>(aptr + k0 + 36);
#pragma unroll
            for (int j = 0; j < 4; j++)
                bv[j] = *reinterpret_cast<const float4*>(bptr + (size_t)(k0 + 32) * CC + j * 4);
        }
#pragma unroll
        for (int kk = 0; kk < 4; kk++) {
            unsigned afr[2][4], bfr[4][2];
#pragma unroll
            for (int mt = 0; mt < 2; mt++) {
                int ab = (wm * 32 + mt * 16 + g) * 36 + kk * 8 + t;
                afr[mt][0] = As[ab];       afr[mt][1] = As[ab + 288];
                afr[mt][2] = As[ab + 4];   afr[mt][3] = As[ab + 292];
            }
#pragma unroll
            for (int nt = 0; nt < 4; nt++) {
                int col = wn * 32 + nt * 8 + g;
                int bb = (kk * 8 + t) * 136 + col;
                bfr[nt][0] = Bs[bb];
                bfr[nt][1] = Bs[bb + 544];
            }
#pragma unroll
            for (int mt = 0; mt < 2; mt++)
#pragma unroll
                for (int nt = 0; nt < 4; nt++) mma_tf32(acc[mt][nt], afr[mt], bfr[nt]);
        }
    }
#pragma unroll
    for (int mt = 0; mt < 2; mt++) {
        int r0 = row0 + wm * 32 + mt * 16 + g;
#pragma unroll
        for (int half = 0; half < 2; half++) {
            int grr = r0 + half * 8;
            if (grr < m) {
                int tk = g_tok[e * NN + grr];
                float wgt = g_twt[e * NN + grr];
                float* orow = out + (size_t)tk * CC + cb;
#pragma unroll
                for (int nt = 0; nt < 4; nt++) {
                    int c = wn * 32 + nt * 8 + t * 2;
                    atomicAdd(&orow[c],     wgt * acc[mt][nt][half * 2]);
                    atomicAdd(&orow[c + 1], wgt * acc[mt][nt][half * 2 + 1]);
                }
            }
        }
    }
}

// ---------------- flash attention, split-KV, tf32-mma QK^T -----------------
#define TQ 64
#define TK 64
#define QSTR 132   // Qs stride (tf32 words)
#define KSTR 68    // Kt stride (tf32 words), Kt[h][c]
#define SSTR 68    // St stride (floats), St[c][r] (S transposed)

__global__ void __launch_bounds__(256) attn_kernel() {
    extern __shared__ float sm[];
    unsigned* Qs = reinterpret_cast<unsigned*>(sm);      // [TQ][QSTR] tf32
    unsigned* Kt = Qs + TQ * QSTR;                       // [HH][KSTR] tf32
    float* Vs = reinterpret_cast<float*>(Kt + HH * KSTR);// [TK][HH]
    float* St = Vs + TK * HH;                            // [TK][SSTR] = S^T
    float* mrow = St + TK * SSTR;                        // [TQ]
    float* lrow = mrow + TQ;
    float* crow = lrow + TQ;

    int b = blockIdx.y;
    int wrk = blockIdx.x;
    int qt = 0;
    while (wrk >= (qt >> 3) + 1) { wrk -= (qt >> 3) + 1; qt++; }
    int ch = wrk;
    int q0 = qt * TQ;
    int kv0 = ch * 512;
    int kv1 = min(kv0 + 512, q0 + TQ);
    int tid = threadIdx.x;
    const float scale = 0.08838834764831845f;  // 1/sqrt(128)

    size_t qbase = ((size_t)(b * TT + q0)) * HH;
    for (int idx = tid; idx < TQ * HH; idx += 256) {
        int r = idx >> 7, h = idx & 127;
        Qs[r * QSTR + h] = f2tf(g_q[qbase + idx]);
    }
    if (tid < TQ) { mrow[tid] = NEGINF; lrow[tid] = 0.f; }

    const int lane = tid & 31, w = tid >> 5;
    const int wm = w & 1, wn = w >> 1;       // wm: 32-row half, wn: 16-col quarter
    const int g = lane >> 2, t = lane & 3;
    const int tm = tid >> 4, tn = tid & 15;  // PV: rows tm*4, h cols tn*8

    float oacc[4][8];
#pragma unroll
    for (int i = 0; i < 4; i++)
#pragma unroll
        for (int j = 0; j < 8; j++) oacc[i][j] = 0.f;

    int ntiles = (kv1 - kv0) >> 6;

    for (int tix = 0; tix < ntiles; tix++) {
        int j0 = kv0 + tix * TK;
        size_t kbase = ((size_t)(b * TT + j0)) * HH;
        __syncthreads();  // prior tile fully consumed before overwrite
        for (int idx = tid; idx < TK * HH; idx += 256) {
            int r = idx >> 7, h = idx & 127;
            Kt[h * KSTR + r] = f2tf(g_k[kbase + idx]);
        }
        for (int idx = tid; idx < TK * HH / 4; idx += 256)
            reinterpret_cast<float4*>(Vs)[idx] =
                reinterpret_cast<const float4*>(g_v + kbase)[idx];
        __syncthreads();

        // ---- S = Q K^T via tf32 mma: per warp 2 m-tiles x 2 n-tiles, 16 ksteps
        {
            float acc[2][2][4];
#pragma unroll
            for (int mt = 0; mt < 2; mt++)
#pragma unroll
                for (int nt = 0; nt < 2; nt++)
#pragma unroll
                    for (int i = 0; i < 4; i++) acc[mt][nt][i] = 0.f;
#pragma unroll
            for (int kk = 0; kk < 16; kk++) {
                unsigned afr[2][4], bfr[2][2];
#pragma unroll
                for (int mt = 0; mt < 2; mt++) {
                    int ab = (wm * 32 + mt * 16 + g) * QSTR + kk * 8 + t;
                    afr[mt][0] = Qs[ab];
                    afr[mt][1] = Qs[ab + 8 * QSTR];
                    afr[mt][2] = Qs[ab + 4];
                    afr[mt][3] = Qs[ab + 8 * QSTR + 4];
                }
#pragma unroll
                for (int nt = 0; nt < 2; nt++) {
                    int col = wn * 16 + nt * 8 + g;
                    int bb = (kk * 8 + t) * KSTR + col;
                    bfr[nt][0] = Kt[bb];
                    bfr[nt][1] = Kt[bb + 4 * KSTR];
                }
#pragma unroll
                for (int mt = 0; mt < 2; mt++)
#pragma unroll
                    for (int nt = 0; nt < 2; nt++)
                        mma_tf32(acc[mt][nt], afr[mt], bfr[nt]);
            }
            // masked, scaled, TRANSPOSED store: St[c][r]
#pragma unroll
            for (int mt = 0; mt < 2; mt++)
#pragma unroll
                for (int nt = 0; nt < 2; nt++) {
                    int rbase = wm * 32 + mt * 16 + g;
                    int cbase = wn * 16 + nt * 8 + t * 2;
#pragma unroll
                    for (int i = 0; i < 4; i++) {
                        int r = rbase + (i >> 1) * 8;
                        int c = cbase + (i & 1);
                        St[c * SSTR + r] =
                            ((j0 + c) <= (q0 + r)) ? acc[mt][nt][i] * scale : NEGINF;
                    }
                }
        }
        __syncthreads();

        // ---- online softmax stats; thread r owns row r (reads St column-wise)
        if (tid < TQ) {
            int r = tid;
            float mold = mrow[r];
            float tmax = NEGINF;
#pragma unroll
            for (int c = 0; c < TK; c++) tmax = fmaxf(tmax, St[c * SSTR + r]);
            float mnew = fmaxf(mold, tmax);
            float corr = __expf(mold - mnew);  // 0 on first tile
            float sum = 0.f;
#pragma unroll
            for (int c = 0; c < TK; c++) {
                float pv = __expf(St[c * SSTR + r] - mnew);
                St[c * SSTR + r] = pv;
                sum += pv;
            }
            lrow[r] = lrow[r] * corr + sum;
            mrow[r] = mnew;
            crow[r] = corr;
        }
        __syncthreads();

        // ---- O = O*corr + P V  (P transposed in St -> LDS.128 loads)
#pragma unroll
        for (int i = 0; i < 4; i++) {
            float cr = crow[tm * 4 + i];
#pragma unroll
            for (int j = 0; j < 8; j++) oacc[i][j] *= cr;
        }
        for (int jj = 0; jj < TK; jj++) {
            float4 p4 = *reinterpret_cast<const float4*>(&St[jj * SSTR + tm * 4]);
            float4 v0 = *reinterpret_cast<const float4*>(&Vs[jj * HH + tn * 8]);
            float4 v1 = *reinterpret_cast<const float4*>(&Vs[jj * HH + tn * 8 + 4]);
            float pr[4] = {p4.x, p4.y, p4.z, p4.w};
#pragma unroll
            for (int i = 0; i < 4; i++) {
                float pv = pr[i];
                oacc[i][0] += pv * v0.x; oacc[i][1] += pv * v0.y;
                oacc[i][2] += pv * v0.z; oacc[i][3] += pv * v0.w;
                oacc[i][4] += pv * v1.x; oacc[i][5] += pv * v1.y;
                oacc[i][6] += pv * v1.z; oacc[i][7] += pv * v1.w;
            }
        }
    }

    int base = ((b * NQT + qt) * 4 + ch) * TQ;
#pragma unroll
    for (int i = 0; i < 4; i++) {
        int r = tm * 4 + i;
        float* orow = g_pO + (size_t)(base + r) * HH + tn * 8;
        *reinterpret_cast<float4*>(orow) =
            make_float4(oacc[i][0], oacc[i][1], oacc[i][2], oacc[i][3]);
        *reinterpret_cast<float4*>(orow + 4) =
            make_float4(oacc[i][4], oacc[i][5], oacc[i][6], oacc[i][7]);
    }
    if (tid < TQ) { g_pm[base + tid] = mrow[tid]; g_pl[base + tid] = lrow[tid]; }
}

__global__ void __launch_bounds__(256) attn_combine_kernel() {
    int qt = blockIdx.x, b = blockIdx.y;
    int nch = (qt >> 3) + 1;
    int base = (b * NQT + qt) * 4 * TQ;
    int q0 = qt * TQ;
    for (int idx = threadIdx.x; idx < TQ * HH; idx += 256) {
        int r = idx >> 7, h = idx & 127;
        float mstar = NEGINF;
        for (int i = 0; i < nch; i++)
            mstar = fmaxf(mstar, g_pm[base + i * TQ + r]);
        float l = 0.f, o = 0.f;
        for (int i = 0; i < nch; i++) {
            float sc = __expf(g_pm[base + i * TQ + r] - mstar);
            l += sc * g_pl[base + i * TQ + r];
            o += sc * g_pO[(size_t)(base + i * TQ + r) * HH + h];
        }
        g_attn[((size_t)(b * TT + q0 + r)) * HH + h] = o / l;
    }
}

// ---------------- launch ---------------------------------------------------
extern "C" void kernel_launch(void* const* d_in, const int* in_sizes, int n_in,
                              void* d_out, int out_size) {
    const float* x   = (const float*)d_in[0];
    const float* sim = (const float*)d_in[1];
    const float* gts = (const float*)d_in[2];
    const float* qp  = (const float*)d_in[3];
    const float* kp  = (const float*)d_in[4];
    const float* vp  = (const float*)d_in[5];
    const float* op  = (const float*)d_in[6];
    const int* minexp = (const int*)d_in[7];
    float* out = (float*)d_out;

    const int attn_smem =
        (TQ * QSTR + HH * KSTR + TK * HH + TK * SSTR + 3 * TQ) * (int)sizeof(float);
    cudaFuncSetAttribute((const void*)attn_kernel,
                         cudaFuncAttributeMaxDynamicSharedMemorySize, attn_smem);

    zero4_kernel<<<4096, 256>>>((float4*)out, (NN * CC) / 4);
    zero_scratch_kernel<<<2048, 256>>>();
    colnorm_kernel<<<1, 256>>>(sim);
    logits_kernel<<<dim3(NN / 64, 8), 256>>>(x, sim);
    select_kernel<<<NN / 8, 256>>>(gts, minexp);

    qkv_mma_kernel<<<dim3(NN / 64, 3, EE), 256>>>(x, qp, kp, vp);

    attn_kernel<<<dim3(80, BB), 256, attn_smem>>>();
    attn_combine_kernel<<<dim3(NQT, BB), 256>>>();

    oproj_mma_kernel<<<dim3(NN / 64, CC / 128, EE), 256>>>(op, out);
}

// round 8
// speedup vs baseline: 3.3918x; 1.0951x over previous
#include <cuda_runtime.h>
#include <math.h>

#define BB 4
#define TT 2048
#define CC 2048
#define HH 128
#define EE 16
#define NN (BB * TT)   // 8192 tokens
#define NQT (TT / 64)  // 32 q-tiles per batch
#define NEGINF (__int_as_float(0xff800000u))

// ---------------- scratch (device globals; no allocation allowed) ----------
__device__ float g_q[NN * HH];
__device__ float g_k[NN * HH];
__device__ float g_v[NN * HH];
__device__ float g_attn[NN * HH];
__device__ float g_invsnorm[EE];
__device__ int   g_cnt[EE];
__device__ int   g_tok[EE * NN];
__device__ float g_twt[EE * NN];
__device__ float g_logp[8 * NN * EE];   // split-K logit partials
__device__ float g_xxp[8 * NN];         // split-K |x|^2 partials
// attention split-KV partials: [B][qt][chunk<=4][64 rows][128]
__device__ float g_pO[BB * NQT * 4 * 64 * HH];
__device__ float g_pm[BB * NQT * 4 * 64];
__device__ float g_pl[BB * NQT * 4 * 64];

// ---------------- helpers ---------------------------------------------------
__device__ __forceinline__ unsigned f2tf(float f) {
    unsigned r;
    asm("cvt.rna.tf32.f32 %0, %1;" : "=r"(r) : "f"(f));
    return r;
}
__device__ __forceinline__ void mma_tf32(float* d, const unsigned* a, const unsigned* b) {
    asm volatile(
        "mma.sync.aligned.m16n8k8.row.col.f32.tf32.tf32.f32 "
        "{%0,%1,%2,%3},{%4,%5,%6,%7},{%8,%9},{%0,%1,%2,%3};"
        : "+f"(d[0]), "+f"(d[1]), "+f"(d[2]), "+f"(d[3])
        : "r"(a[0]), "r"(a[1]), "r"(a[2]), "r"(a[3]), "r"(b[0]), "r"(b[1]));
}
__device__ __forceinline__ void red_add_v2(float* p, float a, float b) {
    asm volatile("red.global.add.v2.f32 [%0], {%1,%2};"
                 :: "l"(p), "f"(a), "f"(b) : "memory");
}

// ---------------- zero kernels --------------------------------------------
__global__ void zero4_kernel(float4* p, int n4) {
    int i = blockIdx.x * blockDim.x + threadIdx.x;
    int stride = gridDim.x * blockDim.x;
    float4 z = make_float4(0.f, 0.f, 0.f, 0.f);
    for (; i < n4; i += stride) p[i] = z;
}
__global__ void zero_scratch_kernel() {
    int i = blockIdx.x * blockDim.x + threadIdx.x;
    int stride = gridDim.x * blockDim.x;
    for (int j = i; j < NN * HH; j += stride) {
        g_q[j] = 0.f; g_k[j] = 0.f; g_v[j] = 0.f;
    }
    if (i < EE) g_cnt[i] = 0;
}

// ---------------- sim_matrix column inverse norms -------------------------
__global__ void colnorm_kernel(const float* __restrict__ sim) {
    int tid = threadIdx.x;
    float acc[EE];
#pragma unroll
    for (int e = 0; e < EE; e++) acc[e] = 0.f;
    for (int c = tid; c < CC; c += 256) {
        float sv[EE];
        const float4* row = reinterpret_cast<const float4*>(sim + (size_t)c * EE);
#pragma unroll
        for (int q = 0; q < 4; q++) *reinterpret_cast<float4*>(&sv[q * 4]) = row[q];
#pragma unroll
        for (int e = 0; e < EE; e++) acc[e] += sv[e] * sv[e];
    }
#pragma unroll
    for (int off = 16; off; off >>= 1)
#pragma unroll
        for (int e = 0; e < EE; e++)
            acc[e] += __shfl_xor_sync(0xffffffffu, acc[e], off);
    __shared__ float ws[8][EE];
    if ((tid & 31) == 0)
#pragma unroll
        for (int e = 0; e < EE; e++) ws[tid >> 5][e] = acc[e];
    __syncthreads();
    if (tid < EE) {
        float s = 0.f;
#pragma unroll
        for (int w = 0; w < 8; w++) s += ws[w][tid];
        g_invsnorm[tid] = 1.f / fmaxf(sqrtf(s), 1e-12f);
    }
}

// ---------------- logits: split-K x8, 64 tokens/block ----------------------
__global__ void __launch_bounds__(256) logits_kernel(const float* __restrict__ x,
                                                     const float* __restrict__ sim) {
    __shared__ float Xs[64][132];
    __shared__ float Ss[128][16];
    int n0 = blockIdx.x * 64;
    int part = blockIdx.y;
    int tid = threadIdx.x;
    int tok = tid >> 2;
    int eg = tid & 3;
    float acc[4] = {0.f, 0.f, 0.f, 0.f};
    float xx = 0.f;
    int cbeg = part * 256;
    for (int c0 = cbeg; c0 < cbeg + 256; c0 += 128) {
        __syncthreads();
        for (int i = tid; i < 512; i += 256)
            reinterpret_cast<float4*>(&Ss[0][0])[i] =
                reinterpret_cast<const float4*>(sim + (size_t)c0 * EE)[i];
        for (int i = tid; i < 2048; i += 256) {
            int r = i >> 5, k4 = i & 31;
            *reinterpret_cast<float4*>(&Xs[r][k4 * 4]) =
                *reinterpret_cast<const float4*>(x + (size_t)(n0 + r) * CC + c0 + k4 * 4);
        }
        __syncthreads();
#pragma unroll 4
        for (int k = 0; k < 128; k++) {
            float xv = Xs[tok][k];
            float4 sv = *reinterpret_cast<const float4*>(&Ss[k][eg * 4]);
            acc[0] += xv * sv.x; acc[1] += xv * sv.y;
            acc[2] += xv * sv.z; acc[3] += xv * sv.w;
            if (eg == 0) xx += xv * xv;
        }
    }
    int n = n0 + tok;
    *reinterpret_cast<float4*>(&g_logp[((size_t)part * NN + n) * EE + eg * 4]) =
        make_float4(acc[0], acc[1], acc[2], acc[3]);
    if (eg == 0) g_xxp[part * NN + n] = xx;
}

// ---------------- selection: warp per token -------------------------------
__global__ void __launch_bounds__(256) select_kernel(const float* __restrict__ gates,
                                                     const int* __restrict__ min_experts_p) {
    int n = blockIdx.x * 8 + (threadIdx.x >> 5);
    int lane = threadIdx.x & 31;
    bool isE = (lane < EE);
    float xx = 0.f;
#pragma unroll
    for (int p8 = 0; p8 < 8; p8++) xx += g_xxp[p8 * NN + n];
    float invx = 1.f / fmaxf(sqrtf(xx), 1e-12f);
    float logit = NEGINF;
    if (isE) {
        float dot = 0.f;
#pragma unroll
        for (int p8 = 0; p8 < 8; p8++)
            dot += g_logp[((size_t)p8 * NN + n) * EE + lane];
        float sig = 1.f / (1.f + __expf(-gates[lane]));
        logit = dot * invx * g_invsnorm[lane] - sig;
    }
    float gated = fmaxf(logit, 0.f);
    bool sel = isE && (logit > 0.f);
    unsigned act = __ballot_sync(0xffffffffu, sel);
    if (act == 0u) {
        int kreq = *min_experts_p;
        kreq = max(1, min(kreq, EE));
        bool chosen = false;
        for (int it = 0; it < kreq; it++) {
            float cand = (isE && !chosen) ? logit : NEGINF;
            float mv = cand;
#pragma unroll
            for (int off = 16; off; off >>= 1)
                mv = fmaxf(mv, __shfl_xor_sync(0xffffffffu, mv, off));
            unsigned bal = __ballot_sync(0xffffffffu, (cand == mv) && (mv != NEGINF));
            int ln = __ffs(bal) - 1;
            if (lane == ln) chosen = true;
        }
        sel = chosen;
    }
    float ml = sel ? gated : NEGINF;
    float mv = ml;
#pragma unroll
    for (int off = 16; off; off >>= 1)
        mv = fmaxf(mv, __shfl_xor_sync(0xffffffffu, mv, off));
    float p = sel ? __expf(gated - mv) : 0.f;
    float sum = p;
#pragma unroll
    for (int off = 16; off; off >>= 1)
        sum += __shfl_xor_sync(0xffffffffu, sum, off);
    if (sel) {
        float w = p / sum;
        int pos = atomicAdd(&g_cnt[lane], 1);
        g_tok[lane * NN + pos] = n;
        g_twt[lane * NN + pos] = w;
    }
}

// ---------------- FUSED QKV grouped GEMM (tf32 mma) ------------------------
// grid (NN/64, EE); block 256. Tile 64x(3x128), K=2048 in chunks of 32.
// A tile gathered/staged ONCE, reused for all three projections.
__global__ void __launch_bounds__(256)
qkv_mma_kernel(const float* __restrict__ x, const float* __restrict__ qp,
               const float* __restrict__ kp, const float* __restrict__ vp) {
    const int e = blockIdx.y;
    const int m = g_cnt[e];
    const int row0 = blockIdx.x * 64;
    if (row0 >= m) return;

    extern __shared__ unsigned qsm[];
    unsigned* As = qsm;            // [64][36]
    unsigned* Bs = qsm + 64 * 36;  // [3][32][136]

    const int tid = threadIdx.x, lane = tid & 31, w = tid >> 5;
    const int wm = w & 1, wn = w >> 1;
    const int g = lane >> 2, t = lane & 3;

    float acc[3][2][4][4];
#pragma unroll
    for (int p = 0; p < 3; p++)
#pragma unroll
        for (int mt = 0; mt < 2; mt++)
#pragma unroll
            for (int nt = 0; nt < 4; nt++)
#pragma unroll
                for (int i = 0; i < 4; i++) acc[p][mt][nt][i] = 0.f;

    const int ar = tid >> 2, akb = (tid & 3) * 8;
    int gr = row0 + ar;
    int tok = g_tok[e * NN + ((gr < m) ? gr : (m - 1))];
    const float* aptr = x + (size_t)tok * CC + akb;
    const int br = tid >> 3, bnb = (tid & 7) * 16;
    const float* bp0 = qp + (size_t)e * CC * HH + (size_t)br * HH + bnb;
    const float* bp1 = kp + (size_t)e * CC * HH + (size_t)br * HH + bnb;
    const float* bp2 = vp + (size_t)e * CC * HH + (size_t)br * HH + bnb;

    // prologue prefetch
    float4 av0 = *reinterpret_cast<const float4*>(aptr);
    float4 av1 = *reinterpret_cast<const float4*>(aptr + 4);
    float4 bv[3][4];
#pragma unroll
    for (int j = 0; j < 4; j++) {
        bv[0][j] = *reinterpret_cast<const float4*>(bp0 + j * 4);
        bv[1][j] = *reinterpret_cast<const float4*>(bp1 + j * 4);
        bv[2][j] = *reinterpret_cast<const float4*>(bp2 + j * 4);
    }

    for (int k0 = 0; k0 < CC; k0 += 32) {
        __syncthreads();
        {
            uint4 u0 = make_uint4(f2tf(av0.x), f2tf(av0.y), f2tf(av0.z), f2tf(av0.w));
            uint4 u1 = make_uint4(f2tf(av1.x), f2tf(av1.y), f2tf(av1.z), f2tf(av1.w));
            *reinterpret_cast<uint4*>(&As[ar * 36 + akb]) = u0;
            *reinterpret_cast<uint4*>(&As[ar * 36 + akb + 4]) = u1;
#pragma unroll
            for (int p = 0; p < 3; p++)
#pragma unroll
                for (int j = 0; j < 4; j++) {
                    uint4 ub = make_uint4(f2tf(bv[p][j].x), f2tf(bv[p][j].y),
                                          f2tf(bv[p][j].z), f2tf(bv[p][j].w));
                    *reinterpret_cast<uint4*>(&Bs[p * 4352 + br * 136 + bnb + j * 4]) = ub;
                }
        }
        __syncthreads();
        if (k0 + 32 < CC) {
            av0 = *reinterpret_cast<const float4*>(aptr + k0 + 32);
            av1 = *reinterpret_cast<const float4*>(aptr + k0 + 36);
            size_t boff = (size_t)(k0 + 32) * HH;
#pragma unroll
            for (int j = 0; j < 4; j++) {
                bv[0][j] = *reinterpret_cast<const float4*>(bp0 + boff + j * 4);
                bv[1][j] = *reinterpret_cast<const float4*>(bp1 + boff + j * 4);
                bv[2][j] = *reinterpret_cast<const float4*>(bp2 + boff + j * 4);
            }
        }
#pragma unroll
        for (int kk = 0; kk < 4; kk++) {
            unsigned afr[2][4];
#pragma unroll
            for (int mt = 0; mt < 2; mt++) {
                int ab = (wm * 32 + mt * 16 + g) * 36 + kk * 8 + t;
                afr[mt][0] = As[ab];       afr[mt][1] = As[ab + 288];
                afr[mt][2] = As[ab + 4];   afr[mt][3] = As[ab + 292];
            }
#pragma unroll
            for (int p = 0; p < 3; p++) {
                unsigned bfr[4][2];
#pragma unroll
                for (int nt = 0; nt < 4; nt++) {
                    int col = wn * 32 + nt * 8 + g;
                    int bb = p * 4352 + (kk * 8 + t) * 136 + col;
                    bfr[nt][0] = Bs[bb];
                    bfr[nt][1] = Bs[bb + 544];
                }
#pragma unroll
                for (int mt = 0; mt < 2; mt++)
#pragma unroll
                    for (int nt = 0; nt < 4; nt++)
                        mma_tf32(acc[p][mt][nt], afr[mt], bfr[nt]);
            }
        }
    }
#pragma unroll
    for (int p = 0; p < 3; p++) {
        float* Out = (p == 0) ? g_q : (p == 1) ? g_k : g_v;
#pragma unroll
        for (int mt = 0; mt < 2; mt++) {
            int r0 = row0 + wm * 32 + mt * 16 + g;
#pragma unroll
            for (int half = 0; half < 2; half++) {
                int grr = r0 + half * 8;
                if (grr < m) {
                    int tk = g_tok[e * NN + grr];
                    float wgt = g_twt[e * NN + grr];
                    float* orow = Out + (size_t)tk * HH;
#pragma unroll
                    for (int nt = 0; nt < 4; nt++) {
                        int c = wn * 32 + nt * 8 + t * 2;
                        red_add_v2(&orow[c], wgt * acc[p][mt][nt][half * 2],
                                   wgt * acc[p][mt][nt][half * 2 + 1]);
                    }
                }
            }
        }
    }
}

// ---------------- o-proj grouped GEMM (tf32 mma) ---------------------------
__global__ void __launch_bounds__(256)
oproj_mma_kernel(const float* __restrict__ op, float* __restrict__ out) {
    const int e = blockIdx.z;
    const int m = g_cnt[e];
    const int row0 = blockIdx.x * 64;
    if (row0 >= m) return;
    const int cb = blockIdx.y * 128;
    const float* B = op + (size_t)e * HH * CC + cb;

    __shared__ unsigned As[64 * 36];
    __shared__ unsigned Bs[32 * 136];

    const int tid = threadIdx.x, lane = tid & 31, w = tid >> 5;
    const int wm = w & 1, wn = w >> 1;
    const int g = lane >> 2, t = lane & 3;

    float acc[2][4][4];
#pragma unroll
    for (int mt = 0; mt < 2; mt++)
#pragma unroll
        for (int nt = 0; nt < 4; nt++)
#pragma unroll
            for (int i = 0; i < 4; i++) acc[mt][nt][i] = 0.f;

    const int ar = tid >> 2, akb = (tid & 3) * 8;
    int gr = row0 + ar;
    int tok = g_tok[e * NN + ((gr < m) ? gr : (m - 1))];
    const float* aptr = g_attn + (size_t)tok * HH + akb;
    const int br = tid >> 3, bnb = (tid & 7) * 16;
    const float* bptr = B + (size_t)br * CC + bnb;

    float4 av0 = *reinterpret_cast<const float4*>(aptr);
    float4 av1 = *reinterpret_cast<const float4*>(aptr + 4);
    float4 bv[4];
#pragma unroll
    for (int j = 0; j < 4; j++)
        bv[j] = *reinterpret_cast<const float4*>(bptr + j * 4);

    for (int k0 = 0; k0 < HH; k0 += 32) {
        __syncthreads();
        {
            uint4 u0 = make_uint4(f2tf(av0.x), f2tf(av0.y), f2tf(av0.z), f2tf(av0.w));
            uint4 u1 = make_uint4(f2tf(av1.x), f2tf(av1.y), f2tf(av1.z), f2tf(av1.w));
            *reinterpret_cast<uint4*>(&As[ar * 36 + akb]) = u0;
            *reinterpret_cast<uint4*>(&As[ar * 36 + akb + 4]) = u1;
#pragma unroll
            for (int j = 0; j < 4; j++) {
                uint4 ub = make_uint4(f2tf(bv[j].x), f2tf(bv[j].y), f2tf(bv[j].z), f2tf(bv[j].w));
                *reinterpret_cast<uint4*>(&Bs[br * 136 + bnb + j * 4]) = ub;
            }
        }
        __syncthreads();
        if (k0 + 32 < HH) {
            av0 = *reinterpret_cast<const float4*>(aptr + k0 + 32);
            av1 = *reinterpret_cast<const float4*>(aptr + k0 + 36);
#pragma unroll
            for (int j = 0; j < 4; j++)
                bv[j] = *reinterpret_cast<const float4*>(bptr + (size_t)(k0 + 32) * CC + j * 4);
        }
#pragma unroll
        for (int kk = 0; kk < 4; kk++) {
            unsigned afr[2][4], bfr[4][2];
#pragma unroll
            for (int mt = 0; mt < 2; mt++) {
                int ab = (wm * 32 + mt * 16 + g) * 36 + kk * 8 + t;
                afr[mt][0] = As[ab];       afr[mt][1] = As[ab + 288];
                afr[mt][2] = As[ab + 4];   afr[mt][3] = As[ab + 292];
            }
#pragma unroll
            for (int nt = 0; nt < 4; nt++) {
                int col = wn * 32 + nt * 8 + g;
                int bb = (kk * 8 + t) * 136 + col;
                bfr[nt][0] = Bs[bb];
                bfr[nt][1] = Bs[bb + 544];
            }
#pragma unroll
            for (int mt = 0; mt < 2; mt++)
#pragma unroll
                for (int nt = 0; nt < 4; nt++) mma_tf32(acc[mt][nt], afr[mt], bfr[nt]);
        }
    }
#pragma unroll
    for (int mt = 0; mt < 2; mt++) {
        int r0 = row0 + wm * 32 + mt * 16 + g;
#pragma unroll
        for (int half = 0; half < 2; half++) {
            int grr = r0 + half * 8;
            if (grr < m) {
                int tk = g_tok[e * NN + grr];
                float wgt = g_twt[e * NN + grr];
                float* orow = out + (size_t)tk * CC + cb;
#pragma unroll
                for (int nt = 0; nt < 4; nt++) {
                    int c = wn * 32 + nt * 8 + t * 2;
                    red_add_v2(&orow[c], wgt * acc[mt][nt][half * 2],
                               wgt * acc[mt][nt][half * 2 + 1]);
                }
            }
        }
    }
}

// ---------------- flash attention, split-KV, full tf32-mma -----------------
#define TQ 64
#define TK 64
#define QSTR 132   // Qs stride (tf32 words)
#define KSTR 68    // Kt stride (tf32 words), Kt[h][c]
#define VSTR 136   // Vt stride (tf32 words), Vt[c][h]
#define SSTR 68    // S/P stride, row-major S[r][c]

__global__ void __launch_bounds__(256) attn_kernel() {
    extern __shared__ float sm[];
    unsigned* Qs = reinterpret_cast<unsigned*>(sm);        // [TQ][QSTR] tf32
    unsigned* Kt = Qs + TQ * QSTR;                         // [HH][KSTR] tf32
    unsigned* Vt = Kt + HH * KSTR;                         // [TK][VSTR] tf32
    float* Ss = reinterpret_cast<float*>(Vt + TK * VSTR);  // [TQ][SSTR] S, then P(tf32 bits)
    unsigned* Pu = reinterpret_cast<unsigned*>(Ss);
    float* mrow = Ss + TQ * SSTR;
    float* lrow = mrow + TQ;
    float* crow = lrow + TQ;

    int b = blockIdx.y;
    int wrk = blockIdx.x;
    int qt = 0;
    while (wrk >= (qt >> 3) + 1) { wrk -= (qt >> 3) + 1; qt++; }
    int ch = wrk;
    int q0 = qt * TQ;
    int kv0 = ch * 512;
    int kv1 = min(kv0 + 512, q0 + TQ);
    int tid = threadIdx.x;
    const float scale = 0.08838834764831845f;  // 1/sqrt(128)

    size_t qbase = ((size_t)(b * TT + q0)) * HH;
    for (int idx = tid; idx < TQ * HH; idx += 256) {
        int r = idx >> 7, h = idx & 127;
        Qs[r * QSTR + h] = f2tf(g_q[qbase + idx]);
    }
    if (tid < TQ) { mrow[tid] = NEGINF; lrow[tid] = 0.f; }

    const int lane = tid & 31, w = tid >> 5;
    const int wm = w & 1, wn = w >> 1;
    const int g = lane >> 2, t = lane & 3;

    // O accumulator as mma D fragments: 2 m-tiles x 4 n-tiles (cols wn*32+nt*8)
    float oacc[2][4][4];
#pragma unroll
    for (int mt = 0; mt < 2; mt++)
#pragma unroll
        for (int nt = 0; nt < 4; nt++)
#pragma unroll
            for (int i = 0; i < 4; i++) oacc[mt][nt][i] = 0.f;

    int ntiles = (kv1 - kv0) >> 6;

    for (int tix = 0; tix < ntiles; tix++) {
        int j0 = kv0 + tix * TK;
        size_t kbase = ((size_t)(b * TT + j0)) * HH;
        __syncthreads();  // prior tile fully consumed
        for (int idx = tid; idx < TK * HH; idx += 256) {
            int r = idx >> 7, h = idx & 127;
            Kt[h * KSTR + r] = f2tf(g_k[kbase + idx]);
            Vt[r * VSTR + h] = f2tf(g_v[kbase + idx]);
        }
        __syncthreads();

        // ---- S = Q K^T via tf32 mma (2 m-tiles x 2 n-tiles of 8, wn covers 16)
        {
            float sacc[2][2][4];
#pragma unroll
            for (int mt = 0; mt < 2; mt++)
#pragma unroll
                for (int nt = 0; nt < 2; nt++)
#pragma unroll
                    for (int i = 0; i < 4; i++) sacc[mt][nt][i] = 0.f;
#pragma unroll
            for (int kk = 0; kk < 16; kk++) {
                unsigned afr[2][4], bfr[2][2];
#pragma unroll
                for (int mt = 0; mt < 2; mt++) {
                    int ab = (wm * 32 + mt * 16 + g) * QSTR + kk * 8 + t;
                    afr[mt][0] = Qs[ab];
                    afr[mt][1] = Qs[ab + 8 * QSTR];
                    afr[mt][2] = Qs[ab + 4];
                    afr[mt][3] = Qs[ab + 8 * QSTR + 4];
                }
#pragma unroll
                for (int nt = 0; nt < 2; nt++) {
                    int col = wn * 16 + nt * 8 + g;
                    int bb = (kk * 8 + t) * KSTR + col;
                    bfr[nt][0] = Kt[bb];
                    bfr[nt][1] = Kt[bb + 4 * KSTR];
                }
#pragma unroll
                for (int mt = 0; mt < 2; mt++)
#pragma unroll
                    for (int nt = 0; nt < 2; nt++)
                        mma_tf32(sacc[mt][nt], afr[mt], bfr[nt]);
            }
            // masked, scaled store, ROW-major: Ss[r][c]
#pragma unroll
            for (int mt = 0; mt < 2; mt++)
#pragma unroll
                for (int nt = 0; nt < 2; nt++) {
                    int rbase = wm * 32 + mt * 16 + g;
                    int cbase = wn * 16 + nt * 8 + t * 2;
#pragma unroll
                    for (int i = 0; i < 4; i++) {
                        int r = rbase + (i >> 1) * 8;
                        int c = cbase + (i & 1);
                        Ss[r * SSTR + c] =
                            ((j0 + c) <= (q0 + r)) ? sacc[mt][nt][i] * scale : NEGINF;
                    }
                }
        }
        __syncthreads();

        // ---- online softmax; thread r owns row r; writes P as tf32 bits
        if (tid < TQ) {
            int r = tid;
            float mold = mrow[r];
            float tmax = NEGINF;
#pragma unroll
            for (int c = 0; c < TK; c++) tmax = fmaxf(tmax, Ss[r * SSTR + c]);
            float mnew = fmaxf(mold, tmax);
            float corr = __expf(mold - mnew);  // 0 on first tile
            float sum = 0.f;
#pragma unroll
            for (int c = 0; c < TK; c++) {
                float pv = __expf(Ss[r * SSTR + c] - mnew);
                Pu[r * SSTR + c] = f2tf(pv);
                sum += pv;
            }
            lrow[r] = lrow[r] * corr + sum;
            mrow[r] = mnew;
            crow[r] = corr;
        }
        __syncthreads();

        // ---- scale O by corr, then O += P V via tf32 mma
#pragma unroll
        for (int mt = 0; mt < 2; mt++) {
            int r0 = wm * 32 + mt * 16 + g;
            float c0 = crow[r0], c1 = crow[r0 + 8];
#pragma unroll
            for (int nt = 0; nt < 4; nt++) {
                oacc[mt][nt][0] *= c0; oacc[mt][nt][1] *= c0;
                oacc[mt][nt][2] *= c1; oacc[mt][nt][3] *= c1;
            }
        }
#pragma unroll
        for (int kk = 0; kk < 8; kk++) {
            unsigned afr[2][4], bfr[4][2];
#pragma unroll
            for (int mt = 0; mt < 2; mt++) {
                int ab = (wm * 32 + mt * 16 + g) * SSTR + kk * 8 + t;
                afr[mt][0] = Pu[ab];
                afr[mt][1] = Pu[ab + 8 * SSTR];
                afr[mt][2] = Pu[ab + 4];
                afr[mt][3] = Pu[ab + 8 * SSTR + 4];
            }
#pragma unroll
            for (int nt = 0; nt < 4; nt++) {
                int col = wn * 32 + nt * 8 + g;
                int bb = (kk * 8 + t) * VSTR + col;
                bfr[nt][0] = Vt[bb];
                bfr[nt][1] = Vt[bb + 4 * VSTR];
            }
#pragma unroll
            for (int mt = 0; mt < 2; mt++)
#pragma unroll
                for (int nt = 0; nt < 4; nt++)
                    mma_tf32(oacc[mt][nt], afr[mt], bfr[nt]);
        }
        __syncthreads();  // Pu/Vt consumed before next tile overwrite
    }

    // epilogue: write unnormalized partial O (fragment layout) + m,l
    int base = ((b * NQT + qt) * 4 + ch) * TQ;
#pragma unroll
    for (int mt = 0; mt < 2; mt++) {
#pragma unroll
        for (int half = 0; half < 2; half++) {
            int r = wm * 32 + mt * 16 + g + half * 8;
            float* orow = g_pO + (size_t)(base + r) * HH;
#pragma unroll
            for (int nt = 0; nt < 4; nt++) {
                int c = wn * 32 + nt * 8 + t * 2;
                *reinterpret_cast<float2*>(&orow[c]) =
                    make_float2(oacc[mt][nt][half * 2], oacc[mt][nt][half * 2 + 1]);
            }
        }
    }
    if (tid < TQ) { g_pm[base + tid] = mrow[tid]; g_pl[base + tid] = lrow[tid]; }
}

__global__ void __launch_bounds__(256) attn_combine_kernel() {
    int qt = blockIdx.x, b = blockIdx.y;
    int nch = (qt >> 3) + 1;
    int base = (b * NQT + qt) * 4 * TQ;
    int q0 = qt * TQ;
    for (int idx = threadIdx.x; idx < TQ * HH; idx += 256) {
        int r = idx >> 7, h = idx & 127;
        float mstar = NEGINF;
        for (int i = 0; i < nch; i++)
            mstar = fmaxf(mstar, g_pm[base + i * TQ + r]);
        float l = 0.f, o = 0.f;
        for (int i = 0; i < nch; i++) {
            float sc = __expf(g_pm[base + i * TQ + r] - mstar);
            l += sc * g_pl[base + i * TQ + r];
            o += sc * g_pO[(size_t)(base + i * TQ + r) * HH + h];
        }
        g_attn[((size_t)(b * TT + q0 + r)) * HH + h] = o / l;
    }
}

// ---------------- launch ---------------------------------------------------
extern "C" void kernel_launch(void* const* d_in, const int* in_sizes, int n_in,
                              void* d_out, int out_size) {
    const float* x   = (const float*)d_in[0];
    const float* sim = (const float*)d_in[1];
    const float* gts = (const float*)d_in[2];
    const float* qp  = (const float*)d_in[3];
    const float* kp  = (const float*)d_in[4];
    const float* vp  = (const float*)d_in[5];
    const float* op  = (const float*)d_in[6];
    const int* minexp = (const int*)d_in[7];
    float* out = (float*)d_out;

    const int attn_smem =
        (TQ * QSTR + HH * KSTR + TK * VSTR + TQ * SSTR + 3 * TQ) * (int)sizeof(float);
    cudaFuncSetAttribute((const void*)attn_kernel,
                         cudaFuncAttributeMaxDynamicSharedMemorySize, attn_smem);
    const int qkv_smem = (64 * 36 + 3 * 32 * 136) * (int)sizeof(unsigned);
    cudaFuncSetAttribute((const void*)qkv_mma_kernel,
                         cudaFuncAttributeMaxDynamicSharedMemorySize, qkv_smem);

    zero4_kernel<<<4096, 256>>>((float4*)out, (NN * CC) / 4);
    zero_scratch_kernel<<<2048, 256>>>();
    colnorm_kernel<<<1, 256>>>(sim);
    logits_kernel<<<dim3(NN / 64, 8), 256>>>(x, sim);
    select_kernel<<<NN / 8, 256>>>(gts, minexp);

    qkv_mma_kernel<<<dim3(NN / 64, EE), 256, qkv_smem>>>(x, qp, kp, vp);

    attn_kernel<<<dim3(80, BB), 256, attn_smem>>>();
    attn_combine_kernel<<<dim3(NQT, BB), 256>>>();

    oproj_mma_kernel<<<dim3(NN / 64, CC / 128, EE), 256>>>(op, out);
}